// round 14
// baseline (speedup 1.0000x reference)
#include <cuda_runtime.h>
#include <math.h>

// ---- problem dims ----
#define NB 48
#define NA 16
#define LL 768            // NB*NA
#define QKVW 384
#define MPOST 2240

// output layout in d_out (floats): policy_flat | q_values | eo
#define OUT_POLICY 0
#define OUT_Q      24576
#define OUT_EO     25344

#define ACT_NONE 0
#define ACT_LEAKY 1
#define ACT_GELU 2
#define ACT_RELU 3

// ---- scratch ----
__device__ __align__(256) float g_H1[LL * 256];
__device__ __align__(256) float g_H2p[2 * LL * 128];
__device__ __align__(256) float g_eaobs[LL * 128];
__device__ __align__(256) float g_eoea[1536 * 128];
__device__ __align__(256) float g_x1d[1536 * 128];
__device__ __align__(256) float g_qkvd[1536 * QKVW];
__device__ __align__(256) float g_aod[MPOST * 128];
__device__ __align__(256) float g_aopd[MPOST * 128];
__device__ __align__(256) float g_qvp[2 * MPOST];
__device__ __align__(256) float g_fO[12 * LL * 32];
__device__ __align__(256) float g_fM[12 * LL];
__device__ __align__(256) float g_fL[12 * LL];
__device__ int g_ctr;

__device__ __forceinline__ int res_map(int m) {
    if (m < 768) return m;
    int t = m - 768;
    if (t >= 1440) return 0;
    int k = t / 96 + 1;
    int r = t % 96;
    int b = r >> 1, c = r & 1;
    int j = c ? (k - 1) : k;
    return 768 + b * 16 + j;
}

// ============================================================================
// smem structs
// ============================================================================
struct G64W {                // 64x64 tile, 512 threads
    float Ar[64][132];       // A row-major
    float Ws[128][68];       // W k-major
    float Wc[64][4][3];      // flash combine weights
};
struct PoleaW {
    float Ar[64][132];
    float Ws[128][68];
    float Pol[64][36];
    float Wp[32][68];
};
struct FlashS {
    float Qs[32][68];
    float Ks[32][68];
    float Vs[64][36];
    float Ss[64][68];
    float Pt[64][68];
    float Ms[64], Ls[64], Cs[64];
};
struct ClsS {
    float Qc[96][36];
    float Kc[96][36];
    float Vc[96][36];
    float Sc[96][97];
};

// ============================================================================
// g64w: 64x64 tile, K=128 resident, 512 threads, 2m x 4n micro (proven warp
// shape at 4 warps/SMSP).
// ============================================================================
template <int ACTI, bool SPLIT, bool RESG, bool COMBINE, bool QHEAD>
__device__ __forceinline__ void g64w(
    G64W& sm, int bx, int by,
    const float* __restrict__ A, int astride,
    const float* __restrict__ W, const float* __restrict__ W2, int wstride,
    const float* __restrict__ bias, const float* __restrict__ bias2,
    const float* __restrict__ Res,
    const float* __restrict__ fO, const float* __restrict__ fM,
    const float* __restrict__ fL,
    const float* __restrict__ qwv, float* __restrict__ qvp,
    float* __restrict__ C, float* __restrict__ C2, float* __restrict__ C3,
    int m_base, int N)
{
    const int tid = threadIdx.x;
    const int tx = tid & 15, ty = tid >> 4;      // ty: 0..31, rows 2*ty, 2*ty+1
    const int m0 = by * 64, n0 = bx * 64;

    if (COMBINE) {
        if (tid < 256) {
            const int r = tid >> 2, h = tid & 3;  // r 0..63
            const int l = m0 + r;
            float mv[3], Lv[3];
            float Mx = -1e30f;
#pragma unroll
            for (int q = 0; q < 3; q++) {
                mv[q] = fM[(q * 4 + h) * LL + l];
                Lv[q] = fL[(q * 4 + h) * LL + l];
                Mx = fmaxf(Mx, mv[q]);
            }
            float den = 0.f, wq[3];
#pragma unroll
            for (int q = 0; q < 3; q++) { wq[q] = __expf(mv[q] - Mx); den += wq[q] * Lv[q]; }
            const float inv = 1.0f / den;
#pragma unroll
            for (int q = 0; q < 3; q++) sm.Wc[r][h][q] = wq[q] * inv;
        }
        __syncthreads();
    }

    // fill A (64 rows x 128 cols, row-major): 2048 float4 slots / 512 thr
#pragma unroll
    for (int t = 0; t < 4; t++) {
        const int f = tid + t * 512;
        const int r = f >> 5, c = (f & 31) * 4;
        float4 v;
        if (COMBINE) {
            const int h = c >> 5, d = c & 31;
            const int l = m0 + r;
            v = make_float4(0.f, 0.f, 0.f, 0.f);
#pragma unroll
            for (int q = 0; q < 3; q++) {
                const float w = sm.Wc[r][h][q];
                const float4 oq = *(const float4*)(fO + ((size_t)(q * 4 + h) * LL + l) * 32 + d);
                v.x += w * oq.x; v.y += w * oq.y; v.z += w * oq.z; v.w += w * oq.w;
            }
        } else {
            v = *(const float4*)(A + (size_t)(m0 + r) * astride + c);
        }
        *(float4*)&sm.Ar[r][c] = v;
    }
    // fill W (64 n-rows x 128 cols -> k-major): 8 threads per n-row
    {
        const int n = tid & 63;
        const int cb = tid >> 6;                 // 0..7
        const int gn = n0 + n;
#pragma unroll
        for (int t = 0; t < 4; t++) {
            const int c = (cb + 8 * t) * 4;
            float4 v;
            if (SPLIT) {
                const float* p = (gn < 256) ? (W  + (size_t)gn * wstride + c)
                                            : (W2 + (size_t)(gn - 256) * wstride + c);
                v = *(const float4*)p;
            } else {
                v = *(const float4*)(W + (size_t)gn * wstride + c);
            }
            sm.Ws[c + 0][n] = v.x; sm.Ws[c + 1][n] = v.y;
            sm.Ws[c + 2][n] = v.z; sm.Ws[c + 3][n] = v.w;
        }
    }
    __syncthreads();

    float acc[2][4];
#pragma unroll
    for (int i = 0; i < 2; i++)
#pragma unroll
        for (int j = 0; j < 4; j++) acc[i][j] = 0.f;

    const float* a0p = &sm.Ar[ty * 2][0];
    const float* a1p = &sm.Ar[ty * 2 + 1][0];
#pragma unroll 32
    for (int kk = 0; kk < 128; kk++) {
        const float a0 = a0p[kk];
        const float a1 = a1p[kk];
        const float4 b = *(const float4*)&sm.Ws[kk][tx * 4];
        acc[0][0] += a0 * b.x; acc[0][1] += a0 * b.y;
        acc[0][2] += a0 * b.z; acc[0][3] += a0 * b.w;
        acc[1][0] += a1 * b.x; acc[1][1] += a1 * b.y;
        acc[1][2] += a1 * b.z; acc[1][3] += a1 * b.w;
    }

    float qp[2] = {0.f, 0.f};
#pragma unroll
    for (int i = 0; i < 2; i++) {
        const int m = m0 + ty * 2 + i;
        const int gm = m_base + m;
        const float* rres = nullptr;
        if (RESG) rres = Res + (size_t)res_map(gm) * 128;
#pragma unroll
        for (int j = 0; j < 4; j++) {
            const int n = n0 + tx * 4 + j;
            if (SPLIT) {
                if (n < 256) {
                    float v = acc[i][j] + bias[n];
                    v = (v > 0.f) ? v : 0.01f * v;
                    C[(size_t)m * 256 + n] = v;
                } else {
                    float v = acc[i][j] + bias2[n - 256];
                    C2[(size_t)m * 128 + (n - 256)] = v;
                    C3[(size_t)m * 128 + (n - 256)] = v;
                }
            } else {
                float v = acc[i][j];
                if (bias) v += bias[n];
                if (RESG) v += rres[n];
                if (ACTI == ACT_LEAKY) v = (v > 0.f) ? v : 0.01f * v;
                else if (ACTI == ACT_GELU) v = 0.5f * v * (1.0f + erff(v * 0.70710678118654752f));
                else if (ACTI == ACT_RELU) v = fmaxf(v, 0.f);
                if (QHEAD) qp[i] += v * qwv[n];
                else       C[(size_t)m * N + n] = v;
            }
        }
    }
    if (QHEAD) {
#pragma unroll
        for (int i = 0; i < 2; i++) {
            float s = qp[i];
#pragma unroll
            for (int off = 8; off; off >>= 1) s += __shfl_xor_sync(0xffffffffu, s, off);
            const int gm = m_base + m0 + ty * 2 + i;
            if (tx == 0 && gm < 2208) qvp[bx * MPOST + gm] = s;
        }
    }
}

// ============================================================================
// polea_w: 64-row tile, 512 threads.
// pass1 policy = gelu(leaky(H2p0+H2p1+ab2) @ aw3^T + ab3)
// pass2 ea = policy @ eaw_pol^T + ea_obs
// ============================================================================
__device__ __forceinline__ void polea_w(
    PoleaW& sm, int bx, int by,
    const float* __restrict__ H2p, const float* __restrict__ ab2,
    const float* __restrict__ aw3, const float* __restrict__ ab3,
    const float* __restrict__ eaw, const float* __restrict__ eaobs,
    float* __restrict__ out_policy, float* __restrict__ eoea)
{
    const int tid = threadIdx.x;
    const int tx = tid & 15, ty = tid >> 4;    // ty 0..31, rows 2*ty, 2*ty+1
    const int m0 = by * 64, n0 = bx * 64;

#pragma unroll
    for (int t = 0; t < 4; t++) {
        const int f = tid + t * 512;
        const int r = f >> 5, c = (f & 31) * 4;
        const size_t off = (size_t)(m0 + r) * 128 + c;
        const float4 p0 = *(const float4*)(H2p + off);
        const float4 p1 = *(const float4*)(H2p + (size_t)LL * 128 + off);
        const float4 bb = *(const float4*)(ab2 + c);
        float4 v;
        v.x = p0.x + p1.x + bb.x; v.x = (v.x > 0.f) ? v.x : 0.01f * v.x;
        v.y = p0.y + p1.y + bb.y; v.y = (v.y > 0.f) ? v.y : 0.01f * v.y;
        v.z = p0.z + p1.z + bb.z; v.z = (v.z > 0.f) ? v.z : 0.01f * v.z;
        v.w = p0.w + p1.w + bb.w; v.w = (v.w > 0.f) ? v.w : 0.01f * v.w;
        *(float4*)&sm.Ar[r][c] = v;
    }
    {
        const int n = tid & 63;
        const int cb = tid >> 6;
#pragma unroll
        for (int t = 0; t < 4; t++) {
            const int c = (cb + 8 * t) * 4;
            float4 v = make_float4(0.f, 0.f, 0.f, 0.f);
            if (n < 32) v = *(const float4*)(aw3 + (size_t)n * 128 + c);
            sm.Ws[c + 0][n] = v.x; sm.Ws[c + 1][n] = v.y;
            sm.Ws[c + 2][n] = v.z; sm.Ws[c + 3][n] = v.w;
        }
    }
    __syncthreads();

    {
        float acc0[4] = {0.f, 0.f, 0.f, 0.f};
        float acc1[4] = {0.f, 0.f, 0.f, 0.f};
        const float* ap0 = &sm.Ar[ty * 2][0];
        const float* ap1 = &sm.Ar[ty * 2 + 1][0];
#pragma unroll 32
        for (int kk = 0; kk < 128; kk++) {
            const float a0 = ap0[kk];
            const float a1 = ap1[kk];
            const float4 b = *(const float4*)&sm.Ws[kk][tx * 4];
            acc0[0] += a0 * b.x; acc0[1] += a0 * b.y;
            acc0[2] += a0 * b.z; acc0[3] += a0 * b.w;
            acc1[0] += a1 * b.x; acc1[1] += a1 * b.y;
            acc1[2] += a1 * b.z; acc1[3] += a1 * b.w;
        }
        __syncthreads();
        if (tx < 8) {
#pragma unroll
            for (int j = 0; j < 4; j++) {
                const int n = tx * 4 + j;
                float v0 = acc0[j] + ab3[n];
                v0 = 0.5f * v0 * (1.0f + erff(v0 * 0.70710678118654752f));
                float v1 = acc1[j] + ab3[n];
                v1 = 0.5f * v1 * (1.0f + erff(v1 * 0.70710678118654752f));
                sm.Pol[ty * 2][n] = v0;
                sm.Pol[ty * 2 + 1][n] = v1;
                if (bx == 0) {
                    out_policy[(size_t)(m0 + ty * 2) * 32 + n] = v0;
                    out_policy[(size_t)(m0 + ty * 2 + 1) * 32 + n] = v1;
                }
            }
        }
    }
    __syncthreads();

    for (int idx = tid; idx < 2048; idx += 512) {
        const int k = idx >> 6, n = idx & 63;
        sm.Wp[k][n] = eaw[(size_t)(n0 + n) * 160 + 128 + k];
    }
    __syncthreads();

    {
        float acc[2][4];
#pragma unroll
        for (int i = 0; i < 2; i++)
#pragma unroll
            for (int j = 0; j < 4; j++) acc[i][j] = 0.f;
#pragma unroll
        for (int kk = 0; kk < 32; kk++) {
            const float a0 = sm.Pol[ty * 2][kk];
            const float a1 = sm.Pol[ty * 2 + 1][kk];
            const float4 b = *(const float4*)&sm.Wp[kk][tx * 4];
            acc[0][0] += a0 * b.x; acc[0][1] += a0 * b.y;
            acc[0][2] += a0 * b.z; acc[0][3] += a0 * b.w;
            acc[1][0] += a1 * b.x; acc[1][1] += a1 * b.y;
            acc[1][2] += a1 * b.z; acc[1][3] += a1 * b.w;
        }
#pragma unroll
        for (int i = 0; i < 2; i++) {
            const int m = m0 + ty * 2 + i;
#pragma unroll
            for (int j = 0; j < 4; j++) {
                const int n = n0 + tx * 4 + j;
                eoea[(size_t)(768 + m) * 128 + n] = acc[i][j] + eaobs[(size_t)m * 128 + n];
            }
        }
    }
}

// ============================================================================
// flash_half: R12-proven flash body driven by a 256-thread sub-block (stid).
// Two independent halves per 512-thread CTA share aligned __syncthreads.
// ============================================================================
__device__ __forceinline__ void flash_half(
    FlashS& sm, int stid, int q, int h, int l0,
    const float* __restrict__ qkvd,
    float* __restrict__ fO, float* __restrict__ fM, float* __restrict__ fL)
{
    const float* Qb = qkvd + h * 32;
    const float* Kb = qkvd + 128 + h * 32;
    const float* Vb = qkvd + 256 + h * 32;

#pragma unroll
    for (int t = 0; t < 2; t++) {
        const int f = stid + t * 256;
        const int r = f >> 3, c = (f & 7) * 4;
        float4 v = *(const float4*)(Qb + (size_t)(l0 + r) * QKVW + c);
        sm.Qs[c + 0][r] = v.x; sm.Qs[c + 1][r] = v.y;
        sm.Qs[c + 2][r] = v.z; sm.Qs[c + 3][r] = v.w;
    }
    if (stid < 64) { sm.Ms[stid] = -1e30f; sm.Ls[stid] = 0.f; }

    float O[2][4];
#pragma unroll
    for (int i = 0; i < 2; i++)
#pragma unroll
        for (int j = 0; j < 4; j++) O[i][j] = 0.f;

    const int txA = stid & 15, tyA = stid >> 4;
    const int rB = stid >> 2,  hB = stid & 3;
    const int txC = stid & 7,  tyC = stid >> 3;

    const int mbeg = q * 256;
    for (int m0k = mbeg; m0k < mbeg + 256; m0k += 64) {
        __syncthreads();
#pragma unroll
        for (int t = 0; t < 2; t++) {
            const int f = stid + t * 256;
            const int r = f >> 3, c = (f & 7) * 4;
            float4 kv = *(const float4*)(Kb + (size_t)(m0k + r) * QKVW + c);
            sm.Ks[c + 0][r] = kv.x; sm.Ks[c + 1][r] = kv.y;
            sm.Ks[c + 2][r] = kv.z; sm.Ks[c + 3][r] = kv.w;
            float4 vv = *(const float4*)(Vb + (size_t)(m0k + r) * QKVW + c);
            *(float4*)&sm.Vs[r][c] = vv;
        }
        __syncthreads();

        float fa[4][4];
#pragma unroll
        for (int i = 0; i < 4; i++)
#pragma unroll
            for (int j = 0; j < 4; j++) fa[i][j] = 0.f;
#pragma unroll 8
        for (int d = 0; d < 32; d++) {
            float4 a = *(const float4*)&sm.Qs[d][tyA * 4];
            float4 b = *(const float4*)&sm.Ks[d][txA * 4];
            fa[0][0] += a.x * b.x; fa[0][1] += a.x * b.y; fa[0][2] += a.x * b.z; fa[0][3] += a.x * b.w;
            fa[1][0] += a.y * b.x; fa[1][1] += a.y * b.y; fa[1][2] += a.y * b.z; fa[1][3] += a.y * b.w;
            fa[2][0] += a.z * b.x; fa[2][1] += a.z * b.y; fa[2][2] += a.z * b.z; fa[2][3] += a.z * b.w;
            fa[3][0] += a.w * b.x; fa[3][1] += a.w * b.y; fa[3][2] += a.w * b.z; fa[3][3] += a.w * b.w;
        }
        const float sc = 0.17677669529663687f;
#pragma unroll
        for (int i = 0; i < 4; i++)
#pragma unroll
            for (int j = 0; j < 4; j++)
                sm.Ss[tyA * 4 + i][txA * 4 + j] = fa[i][j] * sc;
        __syncthreads();

        {
            const float* srow = &sm.Ss[rB][hB * 16];
            float mloc = -1e30f;
#pragma unroll
            for (int j = 0; j < 16; j++) mloc = fmaxf(mloc, srow[j]);
            mloc = fmaxf(mloc, __shfl_xor_sync(0xffffffffu, mloc, 1));
            mloc = fmaxf(mloc, __shfl_xor_sync(0xffffffffu, mloc, 2));
            float m_old = sm.Ms[rB];
            float m_new = fmaxf(m_old, mloc);
            float corr = __expf(m_old - m_new);
            float s = 0.f;
#pragma unroll
            for (int j = 0; j < 16; j++) {
                float e = __expf(srow[j] - m_new);
                sm.Pt[hB * 16 + j][rB] = e;
                s += e;
            }
            s += __shfl_xor_sync(0xffffffffu, s, 1);
            s += __shfl_xor_sync(0xffffffffu, s, 2);
            if (hB == 0) {
                sm.Ms[rB] = m_new;
                sm.Ls[rB] = sm.Ls[rB] * corr + s;
                sm.Cs[rB] = corr;
            }
        }
        __syncthreads();

        const float c0 = sm.Cs[tyC * 2];
        const float c1 = sm.Cs[tyC * 2 + 1];
#pragma unroll
        for (int j = 0; j < 4; j++) { O[0][j] *= c0; O[1][j] *= c1; }
#pragma unroll 8
        for (int mm = 0; mm < 64; mm++) {
            const float a0 = sm.Pt[mm][tyC * 2];
            const float a1 = sm.Pt[mm][tyC * 2 + 1];
            float4 b = *(const float4*)&sm.Vs[mm][txC * 4];
            O[0][0] += a0 * b.x; O[0][1] += a0 * b.y; O[0][2] += a0 * b.z; O[0][3] += a0 * b.w;
            O[1][0] += a1 * b.x; O[1][1] += a1 * b.y; O[1][2] += a1 * b.z; O[1][3] += a1 * b.w;
        }
    }

    const int pb = q * 4 + h;
#pragma unroll
    for (int i = 0; i < 2; i++) {
        const int r = tyC * 2 + i;
        const int l = l0 + r;
        *(float4*)(fO + ((size_t)pb * LL + l) * 32 + txC * 4) = *(float4*)&O[i][0];
        if (txC == 0) {
            fM[(size_t)pb * LL + l] = sm.Ms[r];
            fL[(size_t)pb * LL + l] = sm.Ls[r];
        }
    }
}

// ============================================================================
// cls_body: 256 active lanes inside a 512-thread block (uniform syncs)
// ============================================================================
__device__ __forceinline__ void cls_body(
    char* raw, int k, int h,
    const float* __restrict__ qkvd, float* __restrict__ aod)
{
    ClsS& sm = *reinterpret_cast<ClsS*>(raw);
    const int tid = threadIdx.x;

#pragma unroll
    for (int t = 0; t < 2; t++) {
        const int f = tid + t * 512;
        if (f < 768) {
            const int r = f >> 3, c = (f & 7) * 4;
            const int b = r >> 1, cc = r & 1;
            const int j = cc ? (k - 1) : k;
            const float* base = qkvd + (size_t)(768 + b * 16 + j) * QKVW + h * 32 + c;
            *(float4*)&sm.Qc[r][c] = *(const float4*)(base);
            *(float4*)&sm.Kc[r][c] = *(const float4*)(base + 128);
            *(float4*)&sm.Vc[r][c] = *(const float4*)(base + 256);
        }
    }
    __syncthreads();

    if (tid < 256) {
        const int tx = tid & 15, ty = tid >> 4;
        float acc[6][6];
#pragma unroll
        for (int i = 0; i < 6; i++)
#pragma unroll
            for (int j = 0; j < 6; j++) acc[i][j] = 0.f;
#pragma unroll 8
        for (int d = 0; d < 32; d++) {
            float a[6], b[6];
#pragma unroll
            for (int i = 0; i < 6; i++) a[i] = sm.Qc[ty * 6 + i][d];
#pragma unroll
            for (int j = 0; j < 6; j++) b[j] = sm.Kc[tx * 6 + j][d];
#pragma unroll
            for (int i = 0; i < 6; i++)
#pragma unroll
                for (int j = 0; j < 6; j++) acc[i][j] += a[i] * b[j];
        }
        const float scl = 0.17677669529663687f;
#pragma unroll
        for (int i = 0; i < 6; i++)
#pragma unroll
            for (int j = 0; j < 6; j++)
                sm.Sc[ty * 6 + i][tx * 6 + j] = acc[i][j] * scl;
    }
    __syncthreads();

    if (tid < 96) {
        float mx = -1e30f;
#pragma unroll 8
        for (int m = 0; m < 96; m++) mx = fmaxf(mx, sm.Sc[tid][m]);
        const float w0 = (float)k, w1 = (float)(16 - k);
        float s = 0.f;
#pragma unroll 8
        for (int m = 0; m < 96; m++) {
            float w = (m & 1) ? w1 : w0;
            float e = w * __expf(sm.Sc[tid][m] - mx);
            sm.Sc[tid][m] = e;
            s += e;
        }
        const float inv = 1.0f / s;
#pragma unroll 8
        for (int m = 0; m < 96; m++) sm.Sc[tid][m] *= inv;
    }
    __syncthreads();

    if (tid < 256) {
        const int txo = tid & 7, tyo = tid >> 3;
        float o[3][4];
#pragma unroll
        for (int i = 0; i < 3; i++)
#pragma unroll
            for (int j = 0; j < 4; j++) o[i][j] = 0.f;
#pragma unroll 8
        for (int m = 0; m < 96; m++) {
            float a[3];
#pragma unroll
            for (int i = 0; i < 3; i++) a[i] = sm.Sc[tyo * 3 + i][m];
            float4 b = *(const float4*)&sm.Vc[m][txo * 4];
#pragma unroll
            for (int i = 0; i < 3; i++) {
                o[i][0] += a[i] * b.x; o[i][1] += a[i] * b.y;
                o[i][2] += a[i] * b.z; o[i][3] += a[i] * b.w;
            }
        }
#pragma unroll
        for (int i = 0; i < 3; i++) {
            const int row = 768 + (k - 1) * 96 + tyo * 3 + i;
            *(float4*)(aod + (size_t)row * 128 + h * 32 + txo * 4) = *(float4*)&o[i][0];
        }
    }
}

// ============================================================================
// dispatch kernels (512 threads, launch_bounds(512,1))
// ============================================================================
__global__ void __launch_bounds__(512, 1)
k_L1(const float* obs, const float* aw1, const float* ab1,
     const float* eow, const float* eob,
     float* H1, float* out_eo, float* eoea)
{
    extern __shared__ char raw[];
    g64w<ACT_NONE, true, false, false, false>(
        *(G64W*)raw, blockIdx.x % 6, blockIdx.x / 6,
        obs, 128, aw1, eow, 128, ab1, eob, nullptr,
        nullptr, nullptr, nullptr, nullptr, nullptr,
        H1, out_eo, eoea, 0, 384);
}

__global__ void __launch_bounds__(512, 1)
k_L2(const float* H1, const float* aw2, float* H2p,
     const float* obs, const float* eaw, const float* eab, float* eaobs)
{
    extern __shared__ char raw[];
    G64W& sm = *(G64W*)raw;
    const int b = blockIdx.x;
    if (b < 48) {       // H2p split-K partials: 2 kz x (12 my x 2 nx)
        const int kz = b / 24, r = b % 24;
        g64w<ACT_NONE, false, false, false, false>(
            sm, r % 2, r / 2,
            H1 + kz * 128, 256, aw2 + kz * 128, nullptr, 256,
            nullptr, nullptr, nullptr, nullptr, nullptr, nullptr, nullptr, nullptr,
            H2p + (size_t)kz * LL * 128, nullptr, nullptr, 0, 128);
    } else if (b < 72) {   // eaobs
        const int r = b - 48;
        g64w<ACT_NONE, false, false, false, false>(
            sm, r % 2, r / 2,
            obs, 128, eaw, nullptr, 160,
            eab, nullptr, nullptr, nullptr, nullptr, nullptr, nullptr, nullptr,
            eaobs, nullptr, nullptr, 0, 128);
    }
}

__global__ void __launch_bounds__(512, 1)
k_L3(const float* H2p, const float* ab2, const float* aw3, const float* ab3,
     const float* eaw, const float* eaobs, float* out_policy, float* eoea,
     const float* riw, const float* rib, float* x1d)
{
    extern __shared__ char raw[];
    const int b = blockIdx.x;
    if (b < 24) {       // polea: 12 my x 2 nx
        polea_w(*(PoleaW*)raw, b % 2, b / 2,
                H2p, ab2, aw3, ab3, eaw, eaobs, out_policy, eoea);
    } else if (b < 48) { // x1 e-rows
        const int r = b - 24;
        g64w<ACT_RELU, false, false, false, false>(
            *(G64W*)raw, r % 2, r / 2,
            eoea, 128, riw, nullptr, 128,
            rib, nullptr, nullptr, nullptr, nullptr, nullptr, nullptr, nullptr,
            x1d, nullptr, nullptr, 0, 128);
    }
}

__global__ void __launch_bounds__(512, 1)
k_L4(const float* eoea, const float* riw, const float* rib, float* x1d,
     const float* miw, const float* mib, float* qkvd)
{
    extern __shared__ char raw[];
    const int b = blockIdx.x;
    if (b < 24) {       // x1 a-rows
        g64w<ACT_RELU, false, false, false, false>(
            *(G64W*)raw, b % 2, b / 2,
            eoea + 768 * 128, 128, riw, nullptr, 128,
            rib, nullptr, nullptr, nullptr, nullptr, nullptr, nullptr, nullptr,
            x1d + 768 * 128, nullptr, nullptr, 768, 128);
    } else if (b < 96) { // qkv e-rows: 12 my x 6 nx
        const int r = b - 24;
        g64w<ACT_NONE, false, false, false, false>(
            *(G64W*)raw, r % 6, r / 6,
            x1d, 128, miw, nullptr, 128,
            mib, nullptr, nullptr, nullptr, nullptr, nullptr, nullptr, nullptr,
            qkvd, nullptr, nullptr, 0, 384);
    }
}

__global__ void __launch_bounds__(512, 1)
k_L5(const float* qkvd, float* fO, float* fM, float* fL,
     const float* x1d, const float* miw, const float* mib, float* qkvd_a)
{
    extern __shared__ char raw[];
    const int b = blockIdx.x;
    if (b < 72) {       // flash: 2 tiles per CTA (paired sub-blocks)
        const int sub = threadIdx.x >> 8;
        const int stid = threadIdx.x & 255;
        const int t = b * 2 + sub;          // 0..143
        const int q = t / 48, rem = t % 48;
        FlashS* smf = reinterpret_cast<FlashS*>(raw) + sub;
        flash_half(*smf, stid, q, rem / 12, (rem % 12) * 64, qkvd, fO, fM, fL);
    } else if (b < 144) { // qkv a-rows: 12 my x 6 nx
        const int r = b - 72;
        g64w<ACT_NONE, false, false, false, false>(
            *(G64W*)raw, r % 6, r / 6,
            x1d + 768 * 128, 128, miw, nullptr, 128,
            mib, nullptr, nullptr, nullptr, nullptr, nullptr, nullptr, nullptr,
            qkvd_a + 768 * QKVW, nullptr, nullptr, 768, 384);
    }
}

__global__ void __launch_bounds__(512, 1)
k_L6(const float* qkvd, float* aod,
     const float* fO, const float* fM, const float* fL,
     const float* x1d, const float* mow, const float* mob, float* aopd)
{
    extern __shared__ char raw[];
    const int b = blockIdx.x;
    if (b < 60) {       // class attention
        cls_body(raw, b % 15 + 1, b / 15, qkvd, aod);
    } else if (b < 84) { // G7 e-rows: out_proj + residual, combine in loader
        const int r = b - 60;
        g64w<ACT_NONE, false, true, true, false>(
            *(G64W*)raw, r % 2, r / 2,
            nullptr, 128, mow, nullptr, 128,
            mob, nullptr, x1d, fO, fM, fL, nullptr, nullptr,
            aopd, nullptr, nullptr, 0, 128);
    }
}

__global__ void __launch_bounds__(512, 1)
k_L7(const float* aod, const float* x1d, const float* mow, const float* mob,
     float* aopd, const float* roww, const float* rob,
     const float* qw, float* qvp)
{
    extern __shared__ char raw[];
    const int b = blockIdx.x;
    if (b < 46) {       // G7 a-rows: 23 my x 2 nx
        g64w<ACT_NONE, false, true, false, false>(
            *(G64W*)raw, b % 2, b / 2,
            aod + 768 * 128, 128, mow, nullptr, 128,
            mob, nullptr, x1d, nullptr, nullptr, nullptr, nullptr, nullptr,
            aopd + 768 * 128, nullptr, nullptr, 768, 128);
    } else if (b < 70) { // G8 e-rows (q-head fused)
        const int r = b - 46;
        g64w<ACT_RELU, false, false, false, true>(
            *(G64W*)raw, r % 2, r / 2,
            aopd, 128, roww, nullptr, 128,
            rob, nullptr, nullptr, nullptr, nullptr, nullptr, qw, qvp,
            nullptr, nullptr, nullptr, 0, 128);
    }
}

__global__ void __launch_bounds__(512, 1)
k_L8(const float* aopd, const float* roww, const float* rob,
     const float* qw, float* qvp, const float* qb, float* out_q)
{
    extern __shared__ char raw[];
    g64w<ACT_RELU, false, false, false, true>(
        *(G64W*)raw, blockIdx.x % 2, blockIdx.x / 2,
        aopd + 768 * 128, 128, roww, nullptr, 128,
        rob, nullptr, nullptr, nullptr, nullptr, nullptr, qw, qvp,
        nullptr, nullptr, nullptr, 768, 128);

    __shared__ int is_last;
    __threadfence();
    __syncthreads();
    if (threadIdx.x == 0) is_last = (atomicAdd(&g_ctr, 1) == gridDim.x - 1);
    __syncthreads();
    if (is_last) {
        if (threadIdx.x == 0) g_ctr = 0;
        __threadfence();
        const float qb0 = qb[0];
        for (int l = threadIdx.x; l < 768; l += 512) {
            const int b = l >> 4, i = l & 15;
            float s = qvp[l] + qvp[MPOST + l] + qb0;
#pragma unroll
            for (int k = 1; k < 16; k++) {
                const int c = (i < k) ? 0 : 1;
                const int row = 768 + (k - 1) * 96 + b * 2 + c;
                s += qvp[row] + qvp[MPOST + row] + qb0;
            }
            out_q[l] = s;
        }
    }
}

extern "C" void kernel_launch(void* const* d_in, const int* in_sizes, int n_in,
                              void* d_out, int out_size)
{
    const float* obs = (const float*)d_in[0];
    const float* aw1 = (const float*)d_in[1];  const float* ab1 = (const float*)d_in[2];
    const float* aw2 = (const float*)d_in[3];  const float* ab2 = (const float*)d_in[4];
    const float* aw3 = (const float*)d_in[5];  const float* ab3 = (const float*)d_in[6];
    const float* eow = (const float*)d_in[7];  const float* eob = (const float*)d_in[8];
    const float* eaw = (const float*)d_in[9];  const float* eab = (const float*)d_in[10];
    const float* riw = (const float*)d_in[11]; const float* rib = (const float*)d_in[12];
    const float* roww = (const float*)d_in[13]; const float* rob = (const float*)d_in[14];
    const float* miw = (const float*)d_in[15]; const float* mib = (const float*)d_in[16];
    const float* mow = (const float*)d_in[17]; const float* mob = (const float*)d_in[18];
    const float* qw  = (const float*)d_in[19]; const float* qb  = (const float*)d_in[20];

    float* out = (float*)d_out;
    float* out_policy = out + OUT_POLICY;
    float* out_q      = out + OUT_Q;
    float* out_eo     = out + OUT_EO;

    float *H1, *H2p, *eaobs, *eoea, *x1d, *qkvd, *aod, *aopd, *qvp, *fO, *fM, *fL;
    cudaGetSymbolAddress((void**)&H1, g_H1);
    cudaGetSymbolAddress((void**)&H2p, g_H2p);
    cudaGetSymbolAddress((void**)&eaobs, g_eaobs);
    cudaGetSymbolAddress((void**)&eoea, g_eoea);
    cudaGetSymbolAddress((void**)&x1d, g_x1d);
    cudaGetSymbolAddress((void**)&qkvd, g_qkvd);
    cudaGetSymbolAddress((void**)&aod, g_aod);
    cudaGetSymbolAddress((void**)&aopd, g_aopd);
    cudaGetSymbolAddress((void**)&qvp, g_qvp);
    cudaGetSymbolAddress((void**)&fO, g_fO);
    cudaGetSymbolAddress((void**)&fM, g_fM);
    cudaGetSymbolAddress((void**)&fL, g_fL);

    const int sG   = (int)sizeof(G64W);
    const int sL3  = (int)(sizeof(PoleaW) > sizeof(G64W) ? sizeof(PoleaW) : sizeof(G64W));
    const int sL5  = (int)(2 * sizeof(FlashS) > sizeof(G64W) ? 2 * sizeof(FlashS) : sizeof(G64W));
    const int sL6  = (int)(sizeof(ClsS) > sizeof(G64W) ? sizeof(ClsS) : sizeof(G64W));

    cudaFuncSetAttribute(k_L1, cudaFuncAttributeMaxDynamicSharedMemorySize, sG);
    cudaFuncSetAttribute(k_L2, cudaFuncAttributeMaxDynamicSharedMemorySize, sG);
    cudaFuncSetAttribute(k_L3, cudaFuncAttributeMaxDynamicSharedMemorySize, sL3);
    cudaFuncSetAttribute(k_L4, cudaFuncAttributeMaxDynamicSharedMemorySize, sG);
    cudaFuncSetAttribute(k_L5, cudaFuncAttributeMaxDynamicSharedMemorySize, sL5);
    cudaFuncSetAttribute(k_L6, cudaFuncAttributeMaxDynamicSharedMemorySize, sL6);
    cudaFuncSetAttribute(k_L7, cudaFuncAttributeMaxDynamicSharedMemorySize, sG);
    cudaFuncSetAttribute(k_L8, cudaFuncAttributeMaxDynamicSharedMemorySize, sG);

    dim3 blk(512);

    k_L1<<<72,  blk, sG >>>(obs, aw1, ab1, eow, eob, H1, out_eo, eoea);
    k_L2<<<72,  blk, sG >>>(H1, aw2, H2p, obs, eaw, eab, eaobs);
    k_L3<<<48,  blk, sL3>>>(H2p, ab2, aw3, ab3, eaw, eaobs, out_policy, eoea,
                            riw, rib, x1d);
    k_L4<<<96,  blk, sG >>>(eoea, riw, rib, x1d, miw, mib, qkvd);
    k_L5<<<144, blk, sL5>>>(qkvd, fO, fM, fL, x1d, miw, mib, qkvd);
    k_L6<<<84,  blk, sL6>>>(qkvd, aod, fO, fM, fL, x1d, mow, mob, aopd);
    k_L7<<<70,  blk, sG >>>(aod, x1d, mow, mob, aopd, roww, rob, qw, qvp);
    k_L8<<<46,  blk, sG >>>(aopd, roww, rob, qw, qvp, qb, out_q);

    (void)in_sizes; (void)n_in; (void)out_size;
}

// round 15
// speedup vs baseline: 1.1722x; 1.1722x over previous
#include <cuda_runtime.h>
#include <math.h>

// ---- problem dims ----
#define NB 48
#define NA 16
#define LL 768            // NB*NA
#define QKVW 384
#define MPOST 2240

// output layout in d_out (floats): policy_flat | q_values | eo
#define OUT_POLICY 0
#define OUT_Q      24576
#define OUT_EO     25344

#define ACT_NONE 0
#define ACT_LEAKY 1
#define ACT_GELU 2
#define ACT_RELU 3

// ---- scratch ----
__device__ __align__(256) float g_H1[LL * 256];
__device__ __align__(256) float g_H2p[2 * LL * 128];
__device__ __align__(256) float g_eaobs[LL * 128];
__device__ __align__(256) float g_eoea[1536 * 128];
__device__ __align__(256) float g_x1d[1536 * 128];
__device__ __align__(256) float g_qkvd[1536 * QKVW];
__device__ __align__(256) float g_aod[MPOST * 128];
__device__ __align__(256) float g_aopd[MPOST * 128];
__device__ __align__(256) float g_qvp[2 * MPOST];
// flash 2-way split partials: [q*4+h][l]
__device__ __align__(256) float g_fO[8 * LL * 32];
__device__ __align__(256) float g_fM[8 * LL];
__device__ __align__(256) float g_fL[8 * LL];
__device__ int g_ctr;

__device__ __forceinline__ int res_map(int m) {
    if (m < 768) return m;
    int t = m - 768;
    if (t >= 1440) return 0;
    int k = t / 96 + 1;
    int r = t % 96;
    int b = r >> 1, c = r & 1;
    int j = c ? (k - 1) : k;
    return 768 + b * 16 + j;
}

// ============================================================================
// smem structs (R12-proven)
// ============================================================================
struct G32F {
    float Ar[32][132];     // A row-major
    float Ws[128][68];     // W k-major, stride 68
    float Wc[32][4][2];    // flash combine weights (2 halves)
};
struct G64F {
    float As[128][68];
    float Ws[128][68];
};
struct PoleaF {
    float Ar[32][132];
    float Ws[128][68];
    float Pol[32][36];
    float Wp[32][68];
};
struct FlashS {
    float Qs[32][68];
    float Ks[32][68];
    float Vs[64][36];
    float Ss[64][68];
    float Pt[64][68];
    float Ms[64], Ls[64], Cs[64];
};
struct ClsS {
    float Qc[96][36];
    float Kc[96][36];
    float Vc[96][36];
    float Sc[96][97];
};

// ============================================================================
// g32_flat: 32x64 tile, K=128 resident, barrier-free mainloop (R12-proven;
// COMBINE now merges 2 flash halves).
// ============================================================================
template <int ACTI, bool SPLIT, bool RESG, bool COMBINE, bool QHEAD>
__device__ __forceinline__ void g32_flat(
    G32F& sm, int bx, int by,
    const float* __restrict__ A, int astride,
    const float* __restrict__ W, const float* __restrict__ W2, int wstride,
    const float* __restrict__ bias, const float* __restrict__ bias2,
    const float* __restrict__ Res,
    const float* __restrict__ fO, const float* __restrict__ fM,
    const float* __restrict__ fL,
    const float* __restrict__ qwv, float* __restrict__ qvp,
    float* __restrict__ C, float* __restrict__ C2, float* __restrict__ C3,
    int m_base, int N)
{
    const int tid = threadIdx.x;
    const int tx = tid & 15, ty = tid >> 4;
    const int m0 = by * 32, n0 = bx * 64;

    if (COMBINE) {
        if (tid < 128) {
            const int r = tid >> 2, h = tid & 3;
            const int l = m0 + r;
            float mv[2], Lv[2];
            float Mx = -1e30f;
#pragma unroll
            for (int q = 0; q < 2; q++) {
                mv[q] = fM[(q * 4 + h) * LL + l];
                Lv[q] = fL[(q * 4 + h) * LL + l];
                Mx = fmaxf(Mx, mv[q]);
            }
            float den = 0.f, wq[2];
#pragma unroll
            for (int q = 0; q < 2; q++) { wq[q] = __expf(mv[q] - Mx); den += wq[q] * Lv[q]; }
            const float inv = 1.0f / den;
#pragma unroll
            for (int q = 0; q < 2; q++) sm.Wc[r][h][q] = wq[q] * inv;
        }
        __syncthreads();
    }

    // fill A (32 rows x 128 cols, row-major, coalesced)
#pragma unroll
    for (int t = 0; t < 4; t++) {
        const int f = tid + t * 256;
        const int r = f >> 5, c = (f & 31) * 4;
        float4 v;
        if (COMBINE) {
            const int h = c >> 5, d = c & 31;
            const int l = m0 + r;
            v = make_float4(0.f, 0.f, 0.f, 0.f);
#pragma unroll
            for (int q = 0; q < 2; q++) {
                const float w = sm.Wc[r][h][q];
                const float4 oq = *(const float4*)(fO + ((size_t)(q * 4 + h) * LL + l) * 32 + d);
                v.x += w * oq.x; v.y += w * oq.y; v.z += w * oq.z; v.w += w * oq.w;
            }
        } else {
            v = *(const float4*)(A + (size_t)(m0 + r) * astride + c);
        }
        *(float4*)&sm.Ar[r][c] = v;
    }
    // fill W (64 rows x 128 cols -> k-major)
    {
        const int n = tid & 63;
        const int cb = tid >> 6;
#pragma unroll
        for (int t = 0; t < 8; t++) {
            const int c = (cb + 4 * t) * 4;
            const int gn = n0 + n;
            float4 v;
            if (SPLIT) {
                const float* p = (gn < 256) ? (W  + (size_t)gn * wstride + c)
                                            : (W2 + (size_t)(gn - 256) * wstride + c);
                v = *(const float4*)p;
            } else {
                v = *(const float4*)(W + (size_t)gn * wstride + c);
            }
            sm.Ws[c + 0][n] = v.x; sm.Ws[c + 1][n] = v.y;
            sm.Ws[c + 2][n] = v.z; sm.Ws[c + 3][n] = v.w;
        }
    }
    __syncthreads();

    float acc[2][4];
#pragma unroll
    for (int i = 0; i < 2; i++)
#pragma unroll
        for (int j = 0; j < 4; j++) acc[i][j] = 0.f;

    const float* a0p = &sm.Ar[ty * 2][0];
    const float* a1p = &sm.Ar[ty * 2 + 1][0];
#pragma unroll 32
    for (int kk = 0; kk < 128; kk++) {
        const float a0 = a0p[kk];
        const float a1 = a1p[kk];
        const float4 b = *(const float4*)&sm.Ws[kk][tx * 4];
        acc[0][0] += a0 * b.x; acc[0][1] += a0 * b.y;
        acc[0][2] += a0 * b.z; acc[0][3] += a0 * b.w;
        acc[1][0] += a1 * b.x; acc[1][1] += a1 * b.y;
        acc[1][2] += a1 * b.z; acc[1][3] += a1 * b.w;
    }

    float qp[2] = {0.f, 0.f};
#pragma unroll
    for (int i = 0; i < 2; i++) {
        const int m = m0 + ty * 2 + i;
        const int gm = m_base + m;
        const float* rres = nullptr;
        if (RESG) rres = Res + (size_t)res_map(gm) * 128;
#pragma unroll
        for (int j = 0; j < 4; j++) {
            const int n = n0 + tx * 4 + j;
            if (SPLIT) {
                if (n < 256) {
                    float v = acc[i][j] + bias[n];
                    v = (v > 0.f) ? v : 0.01f * v;
                    C[(size_t)m * 256 + n] = v;
                } else {
                    float v = acc[i][j] + bias2[n - 256];
                    C2[(size_t)m * 128 + (n - 256)] = v;
                    C3[(size_t)m * 128 + (n - 256)] = v;
                }
            } else {
                float v = acc[i][j];
                if (bias) v += bias[n];
                if (RESG) v += rres[n];
                if (ACTI == ACT_LEAKY) v = (v > 0.f) ? v : 0.01f * v;
                else if (ACTI == ACT_GELU) v = 0.5f * v * (1.0f + erff(v * 0.70710678118654752f));
                else if (ACTI == ACT_RELU) v = fmaxf(v, 0.f);
                if (QHEAD) qp[i] += v * qwv[n];
                else       C[(size_t)m * N + n] = v;
            }
        }
    }
    if (QHEAD) {
#pragma unroll
        for (int i = 0; i < 2; i++) {
            float s = qp[i];
#pragma unroll
            for (int off = 8; off; off >>= 1) s += __shfl_xor_sync(0xffffffffu, s, off);
            const int gm = m_base + m0 + ty * 2 + i;
            if (tx == 0 && gm < 2208) qvp[bx * MPOST + gm] = s;
        }
    }
}

// ============================================================================
// g64_flat: 64x64 tile, K=128 resident (R12-proven)
// ============================================================================
__device__ __forceinline__ void g64_flat(
    G64F& sm, int bx, int by,
    const float* __restrict__ A, const float* __restrict__ W,
    const float* __restrict__ bias, float* __restrict__ C, int N)
{
    const int tid = threadIdx.x;
    const int tx = tid & 15, ty = tid >> 4;
    const int m0 = by * 64, n0 = bx * 64;

    {
        const int r = tid & 63;
        const int cb = tid >> 6;
#pragma unroll
        for (int t = 0; t < 8; t++) {
            const int c = (cb + 4 * t) * 4;
            float4 va = *(const float4*)(A + (size_t)(m0 + r) * 128 + c);
            sm.As[c + 0][r] = va.x; sm.As[c + 1][r] = va.y;
            sm.As[c + 2][r] = va.z; sm.As[c + 3][r] = va.w;
            float4 vw = *(const float4*)(W + (size_t)(n0 + r) * 128 + c);
            sm.Ws[c + 0][r] = vw.x; sm.Ws[c + 1][r] = vw.y;
            sm.Ws[c + 2][r] = vw.z; sm.Ws[c + 3][r] = vw.w;
        }
    }
    __syncthreads();

    float acc[4][4];
#pragma unroll
    for (int i = 0; i < 4; i++)
#pragma unroll
        for (int j = 0; j < 4; j++) acc[i][j] = 0.f;

#pragma unroll 16
    for (int kk = 0; kk < 128; kk++) {
        const float4 a = *(const float4*)&sm.As[kk][ty * 4];
        const float4 b = *(const float4*)&sm.Ws[kk][tx * 4];
        acc[0][0] += a.x * b.x; acc[0][1] += a.x * b.y; acc[0][2] += a.x * b.z; acc[0][3] += a.x * b.w;
        acc[1][0] += a.y * b.x; acc[1][1] += a.y * b.y; acc[1][2] += a.y * b.z; acc[1][3] += a.y * b.w;
        acc[2][0] += a.z * b.x; acc[2][1] += a.z * b.y; acc[2][2] += a.z * b.z; acc[2][3] += a.z * b.w;
        acc[3][0] += a.w * b.x; acc[3][1] += a.w * b.y; acc[3][2] += a.w * b.z; acc[3][3] += a.w * b.w;
    }

#pragma unroll
    for (int i = 0; i < 4; i++) {
        const int m = m0 + ty * 4 + i;
#pragma unroll
        for (int j = 0; j < 4; j++) {
            const int n = n0 + tx * 4 + j;
            C[(size_t)m * N + n] = acc[i][j] + bias[n];
        }
    }
}

// ============================================================================
// polea_flat (R12-proven)
// ============================================================================
__device__ __forceinline__ void polea_flat(
    PoleaF& sm, int bx, int by,
    const float* __restrict__ H2p, const float* __restrict__ ab2,
    const float* __restrict__ aw3, const float* __restrict__ ab3,
    const float* __restrict__ eaw, const float* __restrict__ eaobs,
    float* __restrict__ out_policy, float* __restrict__ eoea)
{
    const int tid = threadIdx.x;
    const int tx = tid & 15, ty = tid >> 4;
    const int m0 = by * 32, n0 = bx * 64;

#pragma unroll
    for (int t = 0; t < 4; t++) {
        const int f = tid + t * 256;
        const int r = f >> 5, c = (f & 31) * 4;
        const size_t off = (size_t)(m0 + r) * 128 + c;
        const float4 p0 = *(const float4*)(H2p + off);
        const float4 p1 = *(const float4*)(H2p + (size_t)LL * 128 + off);
        const float4 bb = *(const float4*)(ab2 + c);
        float4 v;
        v.x = p0.x + p1.x + bb.x; v.x = (v.x > 0.f) ? v.x : 0.01f * v.x;
        v.y = p0.y + p1.y + bb.y; v.y = (v.y > 0.f) ? v.y : 0.01f * v.y;
        v.z = p0.z + p1.z + bb.z; v.z = (v.z > 0.f) ? v.z : 0.01f * v.z;
        v.w = p0.w + p1.w + bb.w; v.w = (v.w > 0.f) ? v.w : 0.01f * v.w;
        *(float4*)&sm.Ar[r][c] = v;
    }
    {
        const int n = tid & 63;
        const int cb = tid >> 6;
#pragma unroll
        for (int t = 0; t < 8; t++) {
            const int c = (cb + 4 * t) * 4;
            float4 v = make_float4(0.f, 0.f, 0.f, 0.f);
            if (n < 32) v = *(const float4*)(aw3 + (size_t)n * 128 + c);
            sm.Ws[c + 0][n] = v.x; sm.Ws[c + 1][n] = v.y;
            sm.Ws[c + 2][n] = v.z; sm.Ws[c + 3][n] = v.w;
        }
    }
    __syncthreads();

    {
        float acc[4] = {0.f, 0.f, 0.f, 0.f};
        float acc1[4] = {0.f, 0.f, 0.f, 0.f};
        const float* ap = &sm.Ar[ty * 2][0];
        const float* ap1 = &sm.Ar[ty * 2 + 1][0];
#pragma unroll 32
        for (int kk = 0; kk < 128; kk++) {
            const float a0 = ap[kk];
            const float a1 = ap1[kk];
            const float4 b = *(const float4*)&sm.Ws[kk][tx * 4];
            acc[0] += a0 * b.x; acc[1] += a0 * b.y;
            acc[2] += a0 * b.z; acc[3] += a0 * b.w;
            acc1[0] += a1 * b.x; acc1[1] += a1 * b.y;
            acc1[2] += a1 * b.z; acc1[3] += a1 * b.w;
        }
        __syncthreads();
        if (tx < 8) {
#pragma unroll
            for (int j = 0; j < 4; j++) {
                const int n = tx * 4 + j;
                float v0 = acc[j] + ab3[n];
                v0 = 0.5f * v0 * (1.0f + erff(v0 * 0.70710678118654752f));
                float v1 = acc1[j] + ab3[n];
                v1 = 0.5f * v1 * (1.0f + erff(v1 * 0.70710678118654752f));
                sm.Pol[ty * 2][n] = v0;
                sm.Pol[ty * 2 + 1][n] = v1;
                if (bx == 0) {
                    out_policy[(size_t)(m0 + ty * 2) * 32 + n] = v0;
                    out_policy[(size_t)(m0 + ty * 2 + 1) * 32 + n] = v1;
                }
            }
        }
    }
    __syncthreads();

    for (int idx = tid; idx < 2048; idx += 256) {
        const int k = idx >> 6, n = idx & 63;
        sm.Wp[k][n] = eaw[(size_t)(n0 + n) * 160 + 128 + k];
    }
    __syncthreads();

    {
        float acc[2][4];
#pragma unroll
        for (int i = 0; i < 2; i++)
#pragma unroll
            for (int j = 0; j < 4; j++) acc[i][j] = 0.f;
#pragma unroll
        for (int kk = 0; kk < 32; kk++) {
            const float a0 = sm.Pol[ty * 2][kk];
            const float a1 = sm.Pol[ty * 2 + 1][kk];
            const float4 b = *(const float4*)&sm.Wp[kk][tx * 4];
            acc[0][0] += a0 * b.x; acc[0][1] += a0 * b.y;
            acc[0][2] += a0 * b.z; acc[0][3] += a0 * b.w;
            acc[1][0] += a1 * b.x; acc[1][1] += a1 * b.y;
            acc[1][2] += a1 * b.z; acc[1][3] += a1 * b.w;
        }
#pragma unroll
        for (int i = 0; i < 2; i++) {
            const int m = m0 + ty * 2 + i;
#pragma unroll
            for (int j = 0; j < 4; j++) {
                const int n = n0 + tx * 4 + j;
                eoea[(size_t)(768 + m) * 128 + n] = acc[i][j] + eaobs[(size_t)m * 128 + n];
            }
        }
    }
}

// ============================================================================
// flash_body: 2-way split-m (384 keys per half), unnormalized partials
// (R5-proven split; R12-proven body)
// ============================================================================
__device__ __forceinline__ void flash_body(
    char* raw, int q, int h, int l0,
    const float* __restrict__ qkvd,
    float* __restrict__ fO, float* __restrict__ fM, float* __restrict__ fL)
{
    FlashS& sm = *reinterpret_cast<FlashS*>(raw);
    const int tid = threadIdx.x;
    const float* Qb = qkvd + h * 32;
    const float* Kb = qkvd + 128 + h * 32;
    const float* Vb = qkvd + 256 + h * 32;

#pragma unroll
    for (int t = 0; t < 2; t++) {
        const int f = tid + t * 256;
        const int r = f >> 3, c = (f & 7) * 4;
        float4 v = *(const float4*)(Qb + (size_t)(l0 + r) * QKVW + c);
        sm.Qs[c + 0][r] = v.x; sm.Qs[c + 1][r] = v.y;
        sm.Qs[c + 2][r] = v.z; sm.Qs[c + 3][r] = v.w;
    }
    if (tid < 64) { sm.Ms[tid] = -1e30f; sm.Ls[tid] = 0.f; }

    float O[2][4];
#pragma unroll
    for (int i = 0; i < 2; i++)
#pragma unroll
        for (int j = 0; j < 4; j++) O[i][j] = 0.f;

    const int txA = tid & 15, tyA = tid >> 4;
    const int rB = tid >> 2,  hB = tid & 3;
    const int txC = tid & 7,  tyC = tid >> 3;

    const int mbeg = q * 384;
    for (int m0k = mbeg; m0k < mbeg + 384; m0k += 64) {
        __syncthreads();
#pragma unroll
        for (int t = 0; t < 2; t++) {
            const int f = tid + t * 256;
            const int r = f >> 3, c = (f & 7) * 4;
            float4 kv = *(const float4*)(Kb + (size_t)(m0k + r) * QKVW + c);
            sm.Ks[c + 0][r] = kv.x; sm.Ks[c + 1][r] = kv.y;
            sm.Ks[c + 2][r] = kv.z; sm.Ks[c + 3][r] = kv.w;
            float4 vv = *(const float4*)(Vb + (size_t)(m0k + r) * QKVW + c);
            *(float4*)&sm.Vs[r][c] = vv;
        }
        __syncthreads();

        float fa[4][4];
#pragma unroll
        for (int i = 0; i < 4; i++)
#pragma unroll
            for (int j = 0; j < 4; j++) fa[i][j] = 0.f;
#pragma unroll 8
        for (int d = 0; d < 32; d++) {
            float4 a = *(const float4*)&sm.Qs[d][tyA * 4];
            float4 b = *(const float4*)&sm.Ks[d][txA * 4];
            fa[0][0] += a.x * b.x; fa[0][1] += a.x * b.y; fa[0][2] += a.x * b.z; fa[0][3] += a.x * b.w;
            fa[1][0] += a.y * b.x; fa[1][1] += a.y * b.y; fa[1][2] += a.y * b.z; fa[1][3] += a.y * b.w;
            fa[2][0] += a.z * b.x; fa[2][1] += a.z * b.y; fa[2][2] += a.z * b.z; fa[2][3] += a.z * b.w;
            fa[3][0] += a.w * b.x; fa[3][1] += a.w * b.y; fa[3][2] += a.w * b.z; fa[3][3] += a.w * b.w;
        }
        const float sc = 0.17677669529663687f;
#pragma unroll
        for (int i = 0; i < 4; i++)
#pragma unroll
            for (int j = 0; j < 4; j++)
                sm.Ss[tyA * 4 + i][txA * 4 + j] = fa[i][j] * sc;
        __syncthreads();

        {
            const float* srow = &sm.Ss[rB][hB * 16];
            float mloc = -1e30f;
#pragma unroll
            for (int j = 0; j < 16; j++) mloc = fmaxf(mloc, srow[j]);
            mloc = fmaxf(mloc, __shfl_xor_sync(0xffffffffu, mloc, 1));
            mloc = fmaxf(mloc, __shfl_xor_sync(0xffffffffu, mloc, 2));
            float m_old = sm.Ms[rB];
            float m_new = fmaxf(m_old, mloc);
            float corr = __expf(m_old - m_new);
            float s = 0.f;
#pragma unroll
            for (int j = 0; j < 16; j++) {
                float e = __expf(srow[j] - m_new);
                sm.Pt[hB * 16 + j][rB] = e;
                s += e;
            }
            s += __shfl_xor_sync(0xffffffffu, s, 1);
            s += __shfl_xor_sync(0xffffffffu, s, 2);
            if (hB == 0) {
                sm.Ms[rB] = m_new;
                sm.Ls[rB] = sm.Ls[rB] * corr + s;
                sm.Cs[rB] = corr;
            }
        }
        __syncthreads();

        const float c0 = sm.Cs[tyC * 2];
        const float c1 = sm.Cs[tyC * 2 + 1];
#pragma unroll
        for (int j = 0; j < 4; j++) { O[0][j] *= c0; O[1][j] *= c1; }
#pragma unroll 8
        for (int mm = 0; mm < 64; mm++) {
            const float a0 = sm.Pt[mm][tyC * 2];
            const float a1 = sm.Pt[mm][tyC * 2 + 1];
            float4 b = *(const float4*)&sm.Vs[mm][txC * 4];
            O[0][0] += a0 * b.x; O[0][1] += a0 * b.y; O[0][2] += a0 * b.z; O[0][3] += a0 * b.w;
            O[1][0] += a1 * b.x; O[1][1] += a1 * b.y; O[1][2] += a1 * b.z; O[1][3] += a1 * b.w;
        }
    }

    const int pb = q * 4 + h;
#pragma unroll
    for (int i = 0; i < 2; i++) {
        const int r = tyC * 2 + i;
        const int l = l0 + r;
        *(float4*)(fO + ((size_t)pb * LL + l) * 32 + txC * 4) = *(float4*)&O[i][0];
        if (txC == 0) {
            fM[(size_t)pb * LL + l] = sm.Ms[r];
            fL[(size_t)pb * LL + l] = sm.Ls[r];
        }
    }
}

__device__ __forceinline__ void cls_body(
    char* raw, int k, int h,
    const float* __restrict__ qkvd, float* __restrict__ aod)
{
    ClsS& sm = *reinterpret_cast<ClsS*>(raw);
    const int tid = threadIdx.x;

#pragma unroll
    for (int t = 0; t < 3; t++) {
        const int f = tid + t * 256;
        const int r = f >> 3, c = (f & 7) * 4;
        const int b = r >> 1, cc = r & 1;
        const int j = cc ? (k - 1) : k;
        const float* base = qkvd + (size_t)(768 + b * 16 + j) * QKVW + h * 32 + c;
        *(float4*)&sm.Qc[r][c] = *(const float4*)(base);
        *(float4*)&sm.Kc[r][c] = *(const float4*)(base + 128);
        *(float4*)&sm.Vc[r][c] = *(const float4*)(base + 256);
    }
    __syncthreads();

    const int tx = tid & 15, ty = tid >> 4;
    {
        float acc[6][6];
#pragma unroll
        for (int i = 0; i < 6; i++)
#pragma unroll
            for (int j = 0; j < 6; j++) acc[i][j] = 0.f;
#pragma unroll 8
        for (int d = 0; d < 32; d++) {
            float a[6], b[6];
#pragma unroll
            for (int i = 0; i < 6; i++) a[i] = sm.Qc[ty * 6 + i][d];
#pragma unroll
            for (int j = 0; j < 6; j++) b[j] = sm.Kc[tx * 6 + j][d];
#pragma unroll
            for (int i = 0; i < 6; i++)
#pragma unroll
                for (int j = 0; j < 6; j++) acc[i][j] += a[i] * b[j];
        }
        const float scl = 0.17677669529663687f;
#pragma unroll
        for (int i = 0; i < 6; i++)
#pragma unroll
            for (int j = 0; j < 6; j++)
                sm.Sc[ty * 6 + i][tx * 6 + j] = acc[i][j] * scl;
    }
    __syncthreads();

    if (tid < 96) {
        float mx = -1e30f;
#pragma unroll 8
        for (int m = 0; m < 96; m++) mx = fmaxf(mx, sm.Sc[tid][m]);
        const float w0 = (float)k, w1 = (float)(16 - k);
        float s = 0.f;
#pragma unroll 8
        for (int m = 0; m < 96; m++) {
            float w = (m & 1) ? w1 : w0;
            float e = w * __expf(sm.Sc[tid][m] - mx);
            sm.Sc[tid][m] = e;
            s += e;
        }
        const float inv = 1.0f / s;
#pragma unroll 8
        for (int m = 0; m < 96; m++) sm.Sc[tid][m] *= inv;
    }
    __syncthreads();

    const int txo = tid & 7, tyo = tid >> 3;
    float o[3][4];
#pragma unroll
    for (int i = 0; i < 3; i++)
#pragma unroll
        for (int j = 0; j < 4; j++) o[i][j] = 0.f;
#pragma unroll 8
    for (int m = 0; m < 96; m++) {
        float a[3];
#pragma unroll
        for (int i = 0; i < 3; i++) a[i] = sm.Sc[tyo * 3 + i][m];
        float4 b = *(const float4*)&sm.Vc[m][txo * 4];
#pragma unroll
        for (int i = 0; i < 3; i++) {
            o[i][0] += a[i] * b.x; o[i][1] += a[i] * b.y;
            o[i][2] += a[i] * b.z; o[i][3] += a[i] * b.w;
        }
    }
#pragma unroll
    for (int i = 0; i < 3; i++) {
        const int row = 768 + (k - 1) * 96 + tyo * 3 + i;
        *(float4*)(aod + (size_t)row * 128 + h * 32 + txo * 4) = *(float4*)&o[i][0];
    }
}

// ============================================================================
// dispatch kernels (R12 structure; L5 now 168 CTAs with 2-way flash)
// ============================================================================
__global__ void __launch_bounds__(256, 1)
k_L1(const float* obs, const float* aw1, const float* ab1,
     const float* eow, const float* eob,
     float* H1, float* out_eo, float* eoea)
{
    extern __shared__ char raw[];
    g32_flat<ACT_NONE, true, false, false, false>(
        *(G32F*)raw, blockIdx.x % 6, blockIdx.x / 6,
        obs, 128, aw1, eow, 128, ab1, eob, nullptr,
        nullptr, nullptr, nullptr, nullptr, nullptr,
        H1, out_eo, eoea, 0, 384);
}

__global__ void __launch_bounds__(256, 1)
k_L2(const float* H1, const float* aw2, float* H2p,
     const float* obs, const float* eaw, const float* eab, float* eaobs)
{
    extern __shared__ char raw[];
    G32F& sm = *(G32F*)raw;
    const int b = blockIdx.x;
    if (b < 96) {
        const int kz = b / 48, r = b % 48;
        g32_flat<ACT_NONE, false, false, false, false>(
            sm, r % 2, r / 2,
            H1 + kz * 128, 256, aw2 + kz * 128, nullptr, 256,
            nullptr, nullptr, nullptr, nullptr, nullptr, nullptr, nullptr, nullptr,
            H2p + (size_t)kz * LL * 128, nullptr, nullptr, 0, 128);
    } else {
        const int r = b - 96;
        g32_flat<ACT_NONE, false, false, false, false>(
            sm, r % 2, r / 2,
            obs, 128, eaw, nullptr, 160,
            eab, nullptr, nullptr, nullptr, nullptr, nullptr, nullptr, nullptr,
            eaobs, nullptr, nullptr, 0, 128);
    }
}

__global__ void __launch_bounds__(256, 1)
k_L3(const float* H2p, const float* ab2, const float* aw3, const float* ab3,
     const float* eaw, const float* eaobs, float* out_policy, float* eoea,
     const float* riw, const float* rib, float* x1d)
{
    extern __shared__ char raw[];
    const int b = blockIdx.x;
    if (b < 48) {
        polea_flat(*(PoleaF*)raw, b % 2, b / 2,
                   H2p, ab2, aw3, ab3, eaw, eaobs, out_policy, eoea);
    } else {
        const int r = b - 48;
        g32_flat<ACT_RELU, false, false, false, false>(
            *(G32F*)raw, r % 2, r / 2,
            eoea, 128, riw, nullptr, 128,
            rib, nullptr, nullptr, nullptr, nullptr, nullptr, nullptr, nullptr,
            x1d, nullptr, nullptr, 0, 128);
    }
}

__global__ void __launch_bounds__(256, 1)
k_L4(const float* eoea, const float* riw, const float* rib, float* x1d,
     const float* miw, const float* mib, float* qkvd)
{
    extern __shared__ char raw[];
    const int b = blockIdx.x;
    if (b < 48) {
        g32_flat<ACT_RELU, false, false, false, false>(
            *(G32F*)raw, b % 2, b / 2,
            eoea + 768 * 128, 128, riw, nullptr, 128,
            rib, nullptr, nullptr, nullptr, nullptr, nullptr, nullptr, nullptr,
            x1d + 768 * 128, nullptr, nullptr, 768, 128);
    } else {
        const int r = b - 48;
        g64_flat(*(G64F*)raw, r % 6, r / 6, x1d, miw, mib, qkvd, 384);
    }
}

__global__ void __launch_bounds__(256, 1)
k_L5(const float* qkvd, float* fO, float* fM, float* fL,
     const float* x1d, const float* miw, const float* mib, float* qkvd_a)
{
    extern __shared__ char raw[];
    const int b = blockIdx.x;
    if (b < 96) {       // flash halves: q = b/48, tile = b%48
        const int q = b / 48, rem = b % 48;
        flash_body(raw, q, rem / 12, (rem % 12) * 64, qkvd, fO, fM, fL);
    } else {            // qkv a-rows
        const int r = b - 96;
        g64_flat(*(G64F*)raw, r % 6, r / 6,
                 x1d + 768 * 128, miw, mib, qkvd_a + 768 * QKVW, 384);
    }
}

__global__ void __launch_bounds__(256, 1)
k_L6(const float* qkvd, float* aod,
     const float* fO, const float* fM, const float* fL,
     const float* x1d, const float* mow, const float* mob, float* aopd)
{
    extern __shared__ char raw[];
    const int b = blockIdx.x;
    if (b < 60) {
        cls_body(raw, b % 15 + 1, b / 15, qkvd, aod);
    } else {
        const int r = b - 60;
        g32_flat<ACT_NONE, false, true, true, false>(
            *(G32F*)raw, r % 2, r / 2,
            nullptr, 128, mow, nullptr, 128,
            mob, nullptr, x1d, fO, fM, fL, nullptr, nullptr,
            aopd, nullptr, nullptr, 0, 128);
    }
}

__global__ void __launch_bounds__(256, 1)
k_L7(const float* aod, const float* x1d, const float* mow, const float* mob,
     float* aopd, const float* roww, const float* rob,
     const float* qw, float* qvp)
{
    extern __shared__ char raw[];
    const int b = blockIdx.x;
    if (b < 92) {
        g32_flat<ACT_NONE, false, true, false, false>(
            *(G32F*)raw, b % 2, b / 2,
            aod + 768 * 128, 128, mow, nullptr, 128,
            mob, nullptr, x1d, nullptr, nullptr, nullptr, nullptr, nullptr,
            aopd + 768 * 128, nullptr, nullptr, 768, 128);
    } else {
        const int r = b - 92;
        g32_flat<ACT_RELU, false, false, false, true>(
            *(G32F*)raw, r % 2, r / 2,
            aopd, 128, roww, nullptr, 128,
            rob, nullptr, nullptr, nullptr, nullptr, nullptr, qw, qvp,
            nullptr, nullptr, nullptr, 0, 128);
    }
}

__global__ void __launch_bounds__(256, 1)
k_L8(const float* aopd, const float* roww, const float* rob,
     const float* qw, float* qvp, const float* qb, float* out_q)
{
    extern __shared__ char raw[];
    g32_flat<ACT_RELU, false, false, false, true>(
        *(G32F*)raw, blockIdx.x % 2, blockIdx.x / 2,
        aopd + 768 * 128, 128, roww, nullptr, 128,
        rob, nullptr, nullptr, nullptr, nullptr, nullptr, qw, qvp,
        nullptr, nullptr, nullptr, 768, 128);

    __shared__ int is_last;
    __threadfence();
    __syncthreads();
    if (threadIdx.x == 0) is_last = (atomicAdd(&g_ctr, 1) == gridDim.x - 1);
    __syncthreads();
    if (is_last) {
        if (threadIdx.x == 0) g_ctr = 0;
        __threadfence();
        const float qb0 = qb[0];
        for (int l = threadIdx.x; l < 768; l += 256) {
            const int b = l >> 4, i = l & 15;
            float s = qvp[l] + qvp[MPOST + l] + qb0;
#pragma unroll
            for (int k = 1; k < 16; k++) {
                const int c = (i < k) ? 0 : 1;
                const int row = 768 + (k - 1) * 96 + b * 2 + c;
                s += qvp[row] + qvp[MPOST + row] + qb0;
            }
            out_q[l] = s;
        }
    }
}

extern "C" void kernel_launch(void* const* d_in, const int* in_sizes, int n_in,
                              void* d_out, int out_size)
{
    const float* obs = (const float*)d_in[0];
    const float* aw1 = (const float*)d_in[1];  const float* ab1 = (const float*)d_in[2];
    const float* aw2 = (const float*)d_in[3];  const float* ab2 = (const float*)d_in[4];
    const float* aw3 = (const float*)d_in[5];  const float* ab3 = (const float*)d_in[6];
    const float* eow = (const float*)d_in[7];  const float* eob = (const float*)d_in[8];
    const float* eaw = (const float*)d_in[9];  const float* eab = (const float*)d_in[10];
    const float* riw = (const float*)d_in[11]; const float* rib = (const float*)d_in[12];
    const float* roww = (const float*)d_in[13]; const float* rob = (const float*)d_in[14];
    const float* miw = (const float*)d_in[15]; const float* mib = (const float*)d_in[16];
    const float* mow = (const float*)d_in[17]; const float* mob = (const float*)d_in[18];
    const float* qw  = (const float*)d_in[19]; const float* qb  = (const float*)d_in[20];

    float* out = (float*)d_out;
    float* out_policy = out + OUT_POLICY;
    float* out_q      = out + OUT_Q;
    float* out_eo     = out + OUT_EO;

    float *H1, *H2p, *eaobs, *eoea, *x1d, *qkvd, *aod, *aopd, *qvp, *fO, *fM, *fL;
    cudaGetSymbolAddress((void**)&H1, g_H1);
    cudaGetSymbolAddress((void**)&H2p, g_H2p);
    cudaGetSymbolAddress((void**)&eaobs, g_eaobs);
    cudaGetSymbolAddress((void**)&eoea, g_eoea);
    cudaGetSymbolAddress((void**)&x1d, g_x1d);
    cudaGetSymbolAddress((void**)&qkvd, g_qkvd);
    cudaGetSymbolAddress((void**)&aod, g_aod);
    cudaGetSymbolAddress((void**)&aopd, g_aopd);
    cudaGetSymbolAddress((void**)&qvp, g_qvp);
    cudaGetSymbolAddress((void**)&fO, g_fO);
    cudaGetSymbolAddress((void**)&fM, g_fM);
    cudaGetSymbolAddress((void**)&fL, g_fL);

    const int sG32  = (int)sizeof(G32F);
    const int sL3   = (int)(sizeof(PoleaF) > sizeof(G32F) ? sizeof(PoleaF) : sizeof(G32F));
    const int sL45  = (int)(sizeof(G64F) > sizeof(FlashS) ? sizeof(G64F) : sizeof(FlashS));
    const int sL6   = (int)(sizeof(ClsS) > sizeof(G32F) ? sizeof(ClsS) : sizeof(G32F));

    cudaFuncSetAttribute(k_L1, cudaFuncAttributeMaxDynamicSharedMemorySize, sG32);
    cudaFuncSetAttribute(k_L2, cudaFuncAttributeMaxDynamicSharedMemorySize, sG32);
    cudaFuncSetAttribute(k_L3, cudaFuncAttributeMaxDynamicSharedMemorySize, sL3);
    cudaFuncSetAttribute(k_L4, cudaFuncAttributeMaxDynamicSharedMemorySize, sL45);
    cudaFuncSetAttribute(k_L5, cudaFuncAttributeMaxDynamicSharedMemorySize, sL45);
    cudaFuncSetAttribute(k_L6, cudaFuncAttributeMaxDynamicSharedMemorySize, sL6);
    cudaFuncSetAttribute(k_L7, cudaFuncAttributeMaxDynamicSharedMemorySize, sG32);
    cudaFuncSetAttribute(k_L8, cudaFuncAttributeMaxDynamicSharedMemorySize, sG32);

    dim3 blk(256);

    k_L1<<<144, blk, sG32>>>(obs, aw1, ab1, eow, eob, H1, out_eo, eoea);
    k_L2<<<144, blk, sG32>>>(H1, aw2, H2p, obs, eaw, eab, eaobs);
    k_L3<<<96,  blk, sL3 >>>(H2p, ab2, aw3, ab3, eaw, eaobs, out_policy, eoea,
                             riw, rib, x1d);
    k_L4<<<120, blk, sL45>>>(eoea, riw, rib, x1d, miw, mib, qkvd);
    k_L5<<<168, blk, sL45>>>(qkvd, fO, fM, fL, x1d, miw, mib, qkvd);
    k_L6<<<108, blk, sL6 >>>(qkvd, aod, fO, fM, fL, x1d, mow, mob, aopd);
    k_L7<<<140, blk, sG32>>>(aod, x1d, mow, mob, aopd, roww, rob, qw, qvp);
    k_L8<<<92,  blk, sG32>>>(aopd, roww, rob, qw, qvp, qb, out_q);

    (void)in_sizes; (void)n_in; (void)out_size;
}

// round 16
// speedup vs baseline: 1.2881x; 1.0989x over previous
#include <cuda_runtime.h>
#include <math.h>

// ---- problem dims ----
#define NB 48
#define NA 16
#define LL 768            // NB*NA
#define QKVW 384
#define MPOST 2240

// output layout in d_out (floats): policy_flat | q_values | eo
#define OUT_POLICY 0
#define OUT_Q      24576
#define OUT_EO     25344

#define ACT_NONE 0
#define ACT_LEAKY 1
#define ACT_GELU 2
#define ACT_RELU 3

// ---- scratch ----
__device__ __align__(256) float g_H1[LL * 256];
__device__ __align__(256) float g_H2p[2 * LL * 128];
__device__ __align__(256) float g_eaobs[LL * 128];
__device__ __align__(256) float g_eoea[1536 * 128];
__device__ __align__(256) float g_x1d[1536 * 128];
__device__ __align__(256) float g_qkvd[1536 * QKVW];
__device__ __align__(256) float g_aod[MPOST * 128];
__device__ __align__(256) float g_aopd[MPOST * 128];
__device__ __align__(256) float g_qvp[2 * MPOST];
__device__ __align__(256) float g_fO[12 * LL * 32];
__device__ __align__(256) float g_fM[12 * LL];
__device__ __align__(256) float g_fL[12 * LL];
__device__ int g_ctr;

__device__ __forceinline__ int res_map(int m) {
    if (m < 768) return m;
    int t = m - 768;
    if (t >= 1440) return 0;
    int k = t / 96 + 1;
    int r = t % 96;
    int b = r >> 1, c = r & 1;
    int j = c ? (k - 1) : k;
    return 768 + b * 16 + j;
}

// ============================================================================
// smem structs (full K=128 tiles resident, no mainloop barriers)
// ============================================================================
struct G32F {
    float Ar[32][132];     // A row-major
    float Ws[128][68];     // W k-major, stride 68
    float Wc[32][4][3];    // flash combine weights
};
struct G64F {
    float As[128][68];
    float Ws[128][68];
};
struct PoleaF {
    float Ar[32][132];
    float Ws[128][68];
    float Pol[32][36];
    float Wp[32][68];
};
struct FlashS {
    float Qs[32][68];
    float Ks[32][68];
    float Vs[64][36];
    float Ss[64][68];
    float Pt[64][68];
    float Ms[64], Ls[64], Cs[64];
};
struct ClsS {
    float Qc[96][36];
    float Kc[96][36];
    float Vc[96][36];
    float Sc[96][97];
};

// ============================================================================
// g32_flat: 32x64 tile, K=128 resident, barrier-free mainloop.
// ============================================================================
template <int ACTI, bool SPLIT, bool RESG, bool COMBINE, bool QHEAD>
__device__ __forceinline__ void g32_flat(
    G32F& sm, int bx, int by,
    const float* __restrict__ A, int astride,
    const float* __restrict__ W, const float* __restrict__ W2, int wstride,
    const float* __restrict__ bias, const float* __restrict__ bias2,
    const float* __restrict__ Res,
    const float* __restrict__ fO, const float* __restrict__ fM,
    const float* __restrict__ fL,
    const float* __restrict__ qwv, float* __restrict__ qvp,
    float* __restrict__ C, float* __restrict__ C2, float* __restrict__ C3,
    int m_base, int N)
{
    const int tid = threadIdx.x;
    const int tx = tid & 15, ty = tid >> 4;
    const int m0 = by * 32, n0 = bx * 64;

    if (COMBINE) {
        if (tid < 128) {
            const int r = tid >> 2, h = tid & 3;
            const int l = m0 + r;
            float mv[3], Lv[3];
            float Mx = -1e30f;
#pragma unroll
            for (int q = 0; q < 3; q++) {
                mv[q] = fM[(q * 4 + h) * LL + l];
                Lv[q] = fL[(q * 4 + h) * LL + l];
                Mx = fmaxf(Mx, mv[q]);
            }
            float den = 0.f, wq[3];
#pragma unroll
            for (int q = 0; q < 3; q++) { wq[q] = __expf(mv[q] - Mx); den += wq[q] * Lv[q]; }
            const float inv = 1.0f / den;
#pragma unroll
            for (int q = 0; q < 3; q++) sm.Wc[r][h][q] = wq[q] * inv;
        }
        __syncthreads();
    }

    // fill A (32 rows x 128 cols, row-major, coalesced)
#pragma unroll
    for (int t = 0; t < 4; t++) {
        const int f = tid + t * 256;
        const int r = f >> 5, c = (f & 31) * 4;
        float4 v;
        if (COMBINE) {
            const int h = c >> 5, d = c & 31;
            const int l = m0 + r;
            v = make_float4(0.f, 0.f, 0.f, 0.f);
#pragma unroll
            for (int q = 0; q < 3; q++) {
                const float w = sm.Wc[r][h][q];
                const float4 oq = *(const float4*)(fO + ((size_t)(q * 4 + h) * LL + l) * 32 + d);
                v.x += w * oq.x; v.y += w * oq.y; v.z += w * oq.z; v.w += w * oq.w;
            }
        } else {
            v = *(const float4*)(A + (size_t)(m0 + r) * astride + c);
        }
        *(float4*)&sm.Ar[r][c] = v;
    }
    // fill W (64 rows x 128 cols -> k-major)
    {
        const int n = tid & 63;
        const int cb = tid >> 6;
#pragma unroll
        for (int t = 0; t < 8; t++) {
            const int c = (cb + 4 * t) * 4;
            const int gn = n0 + n;
            float4 v;
            if (SPLIT) {
                const float* p = (gn < 256) ? (W  + (size_t)gn * wstride + c)
                                            : (W2 + (size_t)(gn - 256) * wstride + c);
                v = *(const float4*)p;
            } else {
                v = *(const float4*)(W + (size_t)gn * wstride + c);
            }
            sm.Ws[c + 0][n] = v.x; sm.Ws[c + 1][n] = v.y;
            sm.Ws[c + 2][n] = v.z; sm.Ws[c + 3][n] = v.w;
        }
    }
    __syncthreads();

    float acc[2][4];
#pragma unroll
    for (int i = 0; i < 2; i++)
#pragma unroll
        for (int j = 0; j < 4; j++) acc[i][j] = 0.f;

    const float* a0p = &sm.Ar[ty * 2][0];
    const float* a1p = &sm.Ar[ty * 2 + 1][0];
#pragma unroll 32
    for (int kk = 0; kk < 128; kk++) {
        const float a0 = a0p[kk];
        const float a1 = a1p[kk];
        const float4 b = *(const float4*)&sm.Ws[kk][tx * 4];
        acc[0][0] += a0 * b.x; acc[0][1] += a0 * b.y;
        acc[0][2] += a0 * b.z; acc[0][3] += a0 * b.w;
        acc[1][0] += a1 * b.x; acc[1][1] += a1 * b.y;
        acc[1][2] += a1 * b.z; acc[1][3] += a1 * b.w;
    }

    float qp[2] = {0.f, 0.f};
#pragma unroll
    for (int i = 0; i < 2; i++) {
        const int m = m0 + ty * 2 + i;
        const int gm = m_base + m;
        const float* rres = nullptr;
        if (RESG) rres = Res + (size_t)res_map(gm) * 128;
#pragma unroll
        for (int j = 0; j < 4; j++) {
            const int n = n0 + tx * 4 + j;
            if (SPLIT) {
                if (n < 256) {
                    float v = acc[i][j] + bias[n];
                    v = (v > 0.f) ? v : 0.01f * v;
                    C[(size_t)m * 256 + n] = v;
                } else {
                    float v = acc[i][j] + bias2[n - 256];
                    C2[(size_t)m * 128 + (n - 256)] = v;
                    C3[(size_t)m * 128 + (n - 256)] = v;
                }
            } else {
                float v = acc[i][j];
                if (bias) v += bias[n];
                if (RESG) v += rres[n];
                if (ACTI == ACT_LEAKY) v = (v > 0.f) ? v : 0.01f * v;
                else if (ACTI == ACT_GELU) v = 0.5f * v * (1.0f + erff(v * 0.70710678118654752f));
                else if (ACTI == ACT_RELU) v = fmaxf(v, 0.f);
                if (QHEAD) qp[i] += v * qwv[n];
                else       C[(size_t)m * N + n] = v;
            }
        }
    }
    if (QHEAD) {
#pragma unroll
        for (int i = 0; i < 2; i++) {
            float s = qp[i];
#pragma unroll
            for (int off = 8; off; off >>= 1) s += __shfl_xor_sync(0xffffffffu, s, off);
            const int gm = m_base + m0 + ty * 2 + i;
            if (tx == 0 && gm < 2208) qvp[bx * MPOST + gm] = s;
        }
    }
}

// ============================================================================
// g64_flat: 64x64 tile, K=128 resident
// ============================================================================
__device__ __forceinline__ void g64_flat(
    G64F& sm, int bx, int by,
    const float* __restrict__ A, const float* __restrict__ W,
    const float* __restrict__ bias, float* __restrict__ C, int N)
{
    const int tid = threadIdx.x;
    const int tx = tid & 15, ty = tid >> 4;
    const int m0 = by * 64, n0 = bx * 64;

    {
        const int r = tid & 63;
        const int cb = tid >> 6;
#pragma unroll
        for (int t = 0; t < 8; t++) {
            const int c = (cb + 4 * t) * 4;
            float4 va = *(const float4*)(A + (size_t)(m0 + r) * 128 + c);
            sm.As[c + 0][r] = va.x; sm.As[c + 1][r] = va.y;
            sm.As[c + 2][r] = va.z; sm.As[c + 3][r] = va.w;
            float4 vw = *(const float4*)(W + (size_t)(n0 + r) * 128 + c);
            sm.Ws[c + 0][r] = vw.x; sm.Ws[c + 1][r] = vw.y;
            sm.Ws[c + 2][r] = vw.z; sm.Ws[c + 3][r] = vw.w;
        }
    }
    __syncthreads();

    float acc[4][4];
#pragma unroll
    for (int i = 0; i < 4; i++)
#pragma unroll
        for (int j = 0; j < 4; j++) acc[i][j] = 0.f;

#pragma unroll 16
    for (int kk = 0; kk < 128; kk++) {
        const float4 a = *(const float4*)&sm.As[kk][ty * 4];
        const float4 b = *(const float4*)&sm.Ws[kk][tx * 4];
        acc[0][0] += a.x * b.x; acc[0][1] += a.x * b.y; acc[0][2] += a.x * b.z; acc[0][3] += a.x * b.w;
        acc[1][0] += a.y * b.x; acc[1][1] += a.y * b.y; acc[1][2] += a.y * b.z; acc[1][3] += a.y * b.w;
        acc[2][0] += a.z * b.x; acc[2][1] += a.z * b.y; acc[2][2] += a.z * b.z; acc[2][3] += a.z * b.w;
        acc[3][0] += a.w * b.x; acc[3][1] += a.w * b.y; acc[3][2] += a.w * b.z; acc[3][3] += a.w * b.w;
    }

#pragma unroll
    for (int i = 0; i < 4; i++) {
        const int m = m0 + ty * 4 + i;
#pragma unroll
        for (int j = 0; j < 4; j++) {
            const int n = n0 + tx * 4 + j;
            C[(size_t)m * N + n] = acc[i][j] + bias[n];
        }
    }
}

// ============================================================================
// polea_flat
// ============================================================================
__device__ __forceinline__ void polea_flat(
    PoleaF& sm, int bx, int by,
    const float* __restrict__ H2p, const float* __restrict__ ab2,
    const float* __restrict__ aw3, const float* __restrict__ ab3,
    const float* __restrict__ eaw, const float* __restrict__ eaobs,
    float* __restrict__ out_policy, float* __restrict__ eoea)
{
    const int tid = threadIdx.x;
    const int tx = tid & 15, ty = tid >> 4;
    const int m0 = by * 32, n0 = bx * 64;

#pragma unroll
    for (int t = 0; t < 4; t++) {
        const int f = tid + t * 256;
        const int r = f >> 5, c = (f & 31) * 4;
        const size_t off = (size_t)(m0 + r) * 128 + c;
        const float4 p0 = *(const float4*)(H2p + off);
        const float4 p1 = *(const float4*)(H2p + (size_t)LL * 128 + off);
        const float4 bb = *(const float4*)(ab2 + c);
        float4 v;
        v.x = p0.x + p1.x + bb.x; v.x = (v.x > 0.f) ? v.x : 0.01f * v.x;
        v.y = p0.y + p1.y + bb.y; v.y = (v.y > 0.f) ? v.y : 0.01f * v.y;
        v.z = p0.z + p1.z + bb.z; v.z = (v.z > 0.f) ? v.z : 0.01f * v.z;
        v.w = p0.w + p1.w + bb.w; v.w = (v.w > 0.f) ? v.w : 0.01f * v.w;
        *(float4*)&sm.Ar[r][c] = v;
    }
    {
        const int n = tid & 63;
        const int cb = tid >> 6;
#pragma unroll
        for (int t = 0; t < 8; t++) {
            const int c = (cb + 4 * t) * 4;
            float4 v = make_float4(0.f, 0.f, 0.f, 0.f);
            if (n < 32) v = *(const float4*)(aw3 + (size_t)n * 128 + c);
            sm.Ws[c + 0][n] = v.x; sm.Ws[c + 1][n] = v.y;
            sm.Ws[c + 2][n] = v.z; sm.Ws[c + 3][n] = v.w;
        }
    }
    __syncthreads();

    {
        float acc[4] = {0.f, 0.f, 0.f, 0.f};
        float acc1[4] = {0.f, 0.f, 0.f, 0.f};
        const float* ap = &sm.Ar[ty * 2][0];
        const float* ap1 = &sm.Ar[ty * 2 + 1][0];
#pragma unroll 32
        for (int kk = 0; kk < 128; kk++) {
            const float a0 = ap[kk];
            const float a1 = ap1[kk];
            const float4 b = *(const float4*)&sm.Ws[kk][tx * 4];
            acc[0] += a0 * b.x; acc[1] += a0 * b.y;
            acc[2] += a0 * b.z; acc[3] += a0 * b.w;
            acc1[0] += a1 * b.x; acc1[1] += a1 * b.y;
            acc1[2] += a1 * b.z; acc1[3] += a1 * b.w;
        }
        __syncthreads();
        if (tx < 8) {
#pragma unroll
            for (int j = 0; j < 4; j++) {
                const int n = tx * 4 + j;
                float v0 = acc[j] + ab3[n];
                v0 = 0.5f * v0 * (1.0f + erff(v0 * 0.70710678118654752f));
                float v1 = acc1[j] + ab3[n];
                v1 = 0.5f * v1 * (1.0f + erff(v1 * 0.70710678118654752f));
                sm.Pol[ty * 2][n] = v0;
                sm.Pol[ty * 2 + 1][n] = v1;
                if (bx == 0) {
                    out_policy[(size_t)(m0 + ty * 2) * 32 + n] = v0;
                    out_policy[(size_t)(m0 + ty * 2 + 1) * 32 + n] = v1;
                }
            }
        }
    }
    __syncthreads();

    for (int idx = tid; idx < 2048; idx += 256) {
        const int k = idx >> 6, n = idx & 63;
        sm.Wp[k][n] = eaw[(size_t)(n0 + n) * 160 + 128 + k];
    }
    __syncthreads();

    {
        float acc[2][4];
#pragma unroll
        for (int i = 0; i < 2; i++)
#pragma unroll
            for (int j = 0; j < 4; j++) acc[i][j] = 0.f;
#pragma unroll
        for (int kk = 0; kk < 32; kk++) {
            const float a0 = sm.Pol[ty * 2][kk];
            const float a1 = sm.Pol[ty * 2 + 1][kk];
            const float4 b = *(const float4*)&sm.Wp[kk][tx * 4];
            acc[0][0] += a0 * b.x; acc[0][1] += a0 * b.y;
            acc[0][2] += a0 * b.z; acc[0][3] += a0 * b.w;
            acc[1][0] += a1 * b.x; acc[1][1] += a1 * b.y;
            acc[1][2] += a1 * b.z; acc[1][3] += a1 * b.w;
        }
#pragma unroll
        for (int i = 0; i < 2; i++) {
            const int m = m0 + ty * 2 + i;
#pragma unroll
            for (int j = 0; j < 4; j++) {
                const int n = n0 + tx * 4 + j;
                eoea[(size_t)(768 + m) * 128 + n] = acc[i][j] + eaobs[(size_t)m * 128 + n];
            }
        }
    }
}

// ============================================================================
// flash_body: 3-way split-m (256 keys each), unnormalized partials
// ============================================================================
__device__ __forceinline__ void flash_body(
    char* raw, int q, int h, int l0,
    const float* __restrict__ qkvd,
    float* __restrict__ fO, float* __restrict__ fM, float* __restrict__ fL)
{
    FlashS& sm = *reinterpret_cast<FlashS*>(raw);
    const int tid = threadIdx.x;
    const float* Qb = qkvd + h * 32;
    const float* Kb = qkvd + 128 + h * 32;
    const float* Vb = qkvd + 256 + h * 32;

#pragma unroll
    for (int t = 0; t < 2; t++) {
        const int f = tid + t * 256;
        const int r = f >> 3, c = (f & 7) * 4;
        float4 v = *(const float4*)(Qb + (size_t)(l0 + r) * QKVW + c);
        sm.Qs[c + 0][r] = v.x; sm.Qs[c + 1][r] = v.y;
        sm.Qs[c + 2][r] = v.z; sm.Qs[c + 3][r] = v.w;
    }
    if (tid < 64) { sm.Ms[tid] = -1e30f; sm.Ls[tid] = 0.f; }

    float O[2][4];
#pragma unroll
    for (int i = 0; i < 2; i++)
#pragma unroll
        for (int j = 0; j < 4; j++) O[i][j] = 0.f;

    const int txA = tid & 15, tyA = tid >> 4;
    const int rB = tid >> 2,  hB = tid & 3;
    const int txC = tid & 7,  tyC = tid >> 3;

    const int mbeg = q * 256;
    for (int m0k = mbeg; m0k < mbeg + 256; m0k += 64) {
        __syncthreads();
#pragma unroll
        for (int t = 0; t < 2; t++) {
            const int f = tid + t * 256;
            const int r = f >> 3, c = (f & 7) * 4;
            float4 kv = *(const float4*)(Kb + (size_t)(m0k + r) * QKVW + c);
            sm.Ks[c + 0][r] = kv.x; sm.Ks[c + 1][r] = kv.y;
            sm.Ks[c + 2][r] = kv.z; sm.Ks[c + 3][r] = kv.w;
            float4 vv = *(const float4*)(Vb + (size_t)(m0k + r) * QKVW + c);
            *(float4*)&sm.Vs[r][c] = vv;
        }
        __syncthreads();

        float fa[4][4];
#pragma unroll
        for (int i = 0; i < 4; i++)
#pragma unroll
            for (int j = 0; j < 4; j++) fa[i][j] = 0.f;
#pragma unroll 8
        for (int d = 0; d < 32; d++) {
            float4 a = *(const float4*)&sm.Qs[d][tyA * 4];
            float4 b = *(const float4*)&sm.Ks[d][txA * 4];
            fa[0][0] += a.x * b.x; fa[0][1] += a.x * b.y; fa[0][2] += a.x * b.z; fa[0][3] += a.x * b.w;
            fa[1][0] += a.y * b.x; fa[1][1] += a.y * b.y; fa[1][2] += a.y * b.z; fa[1][3] += a.y * b.w;
            fa[2][0] += a.z * b.x; fa[2][1] += a.z * b.y; fa[2][2] += a.z * b.z; fa[2][3] += a.z * b.w;
            fa[3][0] += a.w * b.x; fa[3][1] += a.w * b.y; fa[3][2] += a.w * b.z; fa[3][3] += a.w * b.w;
        }
        const float sc = 0.17677669529663687f;
#pragma unroll
        for (int i = 0; i < 4; i++)
#pragma unroll
            for (int j = 0; j < 4; j++)
                sm.Ss[tyA * 4 + i][txA * 4 + j] = fa[i][j] * sc;
        __syncthreads();

        {
            const float* srow = &sm.Ss[rB][hB * 16];
            float mloc = -1e30f;
#pragma unroll
            for (int j = 0; j < 16; j++) mloc = fmaxf(mloc, srow[j]);
            mloc = fmaxf(mloc, __shfl_xor_sync(0xffffffffu, mloc, 1));
            mloc = fmaxf(mloc, __shfl_xor_sync(0xffffffffu, mloc, 2));
            float m_old = sm.Ms[rB];
            float m_new = fmaxf(m_old, mloc);
            float corr = __expf(m_old - m_new);
            float s = 0.f;
#pragma unroll
            for (int j = 0; j < 16; j++) {
                float e = __expf(srow[j] - m_new);
                sm.Pt[hB * 16 + j][rB] = e;
                s += e;
            }
            s += __shfl_xor_sync(0xffffffffu, s, 1);
            s += __shfl_xor_sync(0xffffffffu, s, 2);
            if (hB == 0) {
                sm.Ms[rB] = m_new;
                sm.Ls[rB] = sm.Ls[rB] * corr + s;
                sm.Cs[rB] = corr;
            }
        }
        __syncthreads();

        const float c0 = sm.Cs[tyC * 2];
        const float c1 = sm.Cs[tyC * 2 + 1];
#pragma unroll
        for (int j = 0; j < 4; j++) { O[0][j] *= c0; O[1][j] *= c1; }
#pragma unroll 8
        for (int mm = 0; mm < 64; mm++) {
            const float a0 = sm.Pt[mm][tyC * 2];
            const float a1 = sm.Pt[mm][tyC * 2 + 1];
            float4 b = *(const float4*)&sm.Vs[mm][txC * 4];
            O[0][0] += a0 * b.x; O[0][1] += a0 * b.y; O[0][2] += a0 * b.z; O[0][3] += a0 * b.w;
            O[1][0] += a1 * b.x; O[1][1] += a1 * b.y; O[1][2] += a1 * b.z; O[1][3] += a1 * b.w;
        }
    }

    const int pb = q * 4 + h;
#pragma unroll
    for (int i = 0; i < 2; i++) {
        const int r = tyC * 2 + i;
        const int l = l0 + r;
        *(float4*)(fO + ((size_t)pb * LL + l) * 32 + txC * 4) = *(float4*)&O[i][0];
        if (txC == 0) {
            fM[(size_t)pb * LL + l] = sm.Ms[r];
            fL[(size_t)pb * LL + l] = sm.Ls[r];
        }
    }
}

__device__ __forceinline__ void cls_body(
    char* raw, int k, int h,
    const float* __restrict__ qkvd, float* __restrict__ aod)
{
    ClsS& sm = *reinterpret_cast<ClsS*>(raw);
    const int tid = threadIdx.x;

#pragma unroll
    for (int t = 0; t < 3; t++) {
        const int f = tid + t * 256;
        const int r = f >> 3, c = (f & 7) * 4;
        const int b = r >> 1, cc = r & 1;
        const int j = cc ? (k - 1) : k;
        const float* base = qkvd + (size_t)(768 + b * 16 + j) * QKVW + h * 32 + c;
        *(float4*)&sm.Qc[r][c] = *(const float4*)(base);
        *(float4*)&sm.Kc[r][c] = *(const float4*)(base + 128);
        *(float4*)&sm.Vc[r][c] = *(const float4*)(base + 256);
    }
    __syncthreads();

    const int tx = tid & 15, ty = tid >> 4;
    {
        float acc[6][6];
#pragma unroll
        for (int i = 0; i < 6; i++)
#pragma unroll
            for (int j = 0; j < 6; j++) acc[i][j] = 0.f;
#pragma unroll 8
        for (int d = 0; d < 32; d++) {
            float a[6], b[6];
#pragma unroll
            for (int i = 0; i < 6; i++) a[i] = sm.Qc[ty * 6 + i][d];
#pragma unroll
            for (int j = 0; j < 6; j++) b[j] = sm.Kc[tx * 6 + j][d];
#pragma unroll
            for (int i = 0; i < 6; i++)
#pragma unroll
                for (int j = 0; j < 6; j++) acc[i][j] += a[i] * b[j];
        }
        const float scl = 0.17677669529663687f;
#pragma unroll
        for (int i = 0; i < 6; i++)
#pragma unroll
            for (int j = 0; j < 6; j++)
                sm.Sc[ty * 6 + i][tx * 6 + j] = acc[i][j] * scl;
    }
    __syncthreads();

    if (tid < 96) {
        float mx = -1e30f;
#pragma unroll 8
        for (int m = 0; m < 96; m++) mx = fmaxf(mx, sm.Sc[tid][m]);
        const float w0 = (float)k, w1 = (float)(16 - k);
        float s = 0.f;
#pragma unroll 8
        for (int m = 0; m < 96; m++) {
            float w = (m & 1) ? w1 : w0;
            float e = w * __expf(sm.Sc[tid][m] - mx);
            sm.Sc[tid][m] = e;
            s += e;
        }
        const float inv = 1.0f / s;
#pragma unroll 8
        for (int m = 0; m < 96; m++) sm.Sc[tid][m] *= inv;
    }
    __syncthreads();

    const int txo = tid & 7, tyo = tid >> 3;
    float o[3][4];
#pragma unroll
    for (int i = 0; i < 3; i++)
#pragma unroll
        for (int j = 0; j < 4; j++) o[i][j] = 0.f;
#pragma unroll 8
    for (int m = 0; m < 96; m++) {
        float a[3];
#pragma unroll
        for (int i = 0; i < 3; i++) a[i] = sm.Sc[tyo * 3 + i][m];
        float4 b = *(const float4*)&sm.Vc[m][txo * 4];
#pragma unroll
        for (int i = 0; i < 3; i++) {
            o[i][0] += a[i] * b.x; o[i][1] += a[i] * b.y;
            o[i][2] += a[i] * b.z; o[i][3] += a[i] * b.w;
        }
    }
#pragma unroll
    for (int i = 0; i < 3; i++) {
        const int row = 768 + (k - 1) * 96 + tyo * 3 + i;
        *(float4*)(aod + (size_t)row * 128 + h * 32 + txo * 4) = *(float4*)&o[i][0];
    }
}

// ============================================================================
// dispatch kernels
// ============================================================================
__global__ void __launch_bounds__(256, 1)
k_L1(const float* obs, const float* aw1, const float* ab1,
     const float* eow, const float* eob,
     float* H1, float* out_eo, float* eoea)
{
    extern __shared__ char raw[];
    g32_flat<ACT_NONE, true, false, false, false>(
        *(G32F*)raw, blockIdx.x % 6, blockIdx.x / 6,
        obs, 128, aw1, eow, 128, ab1, eob, nullptr,
        nullptr, nullptr, nullptr, nullptr, nullptr,
        H1, out_eo, eoea, 0, 384);
}

__global__ void __launch_bounds__(256, 1)
k_L2(const float* H1, const float* aw2, float* H2p,
     const float* obs, const float* eaw, const float* eab, float* eaobs)
{
    extern __shared__ char raw[];
    G32F& sm = *(G32F*)raw;
    const int b = blockIdx.x;
    if (b < 96) {
        const int kz = b / 48, r = b % 48;
        g32_flat<ACT_NONE, false, false, false, false>(
            sm, r % 2, r / 2,
            H1 + kz * 128, 256, aw2 + kz * 128, nullptr, 256,
            nullptr, nullptr, nullptr, nullptr, nullptr, nullptr, nullptr, nullptr,
            H2p + (size_t)kz * LL * 128, nullptr, nullptr, 0, 128);
    } else {
        const int r = b - 96;
        g32_flat<ACT_NONE, false, false, false, false>(
            sm, r % 2, r / 2,
            obs, 128, eaw, nullptr, 160,
            eab, nullptr, nullptr, nullptr, nullptr, nullptr, nullptr, nullptr,
            eaobs, nullptr, nullptr, 0, 128);
    }
}

__global__ void __launch_bounds__(256, 1)
k_L3(const float* H2p, const float* ab2, const float* aw3, const float* ab3,
     const float* eaw, const float* eaobs, float* out_policy, float* eoea,
     const float* riw, const float* rib, float* x1d)
{
    extern __shared__ char raw[];
    const int b = blockIdx.x;
    if (b < 48) {
        polea_flat(*(PoleaF*)raw, b % 2, b / 2,
                   H2p, ab2, aw3, ab3, eaw, eaobs, out_policy, eoea);
    } else {
        const int r = b - 48;
        g32_flat<ACT_RELU, false, false, false, false>(
            *(G32F*)raw, r % 2, r / 2,
            eoea, 128, riw, nullptr, 128,
            rib, nullptr, nullptr, nullptr, nullptr, nullptr, nullptr, nullptr,
            x1d, nullptr, nullptr, 0, 128);
    }
}

__global__ void __launch_bounds__(256, 1)
k_L4(const float* eoea, const float* riw, const float* rib, float* x1d,
     const float* miw, const float* mib, float* qkvd)
{
    extern __shared__ char raw[];
    const int b = blockIdx.x;
    if (b < 48) {
        g32_flat<ACT_RELU, false, false, false, false>(
            *(G32F*)raw, b % 2, b / 2,
            eoea + 768 * 128, 128, riw, nullptr, 128,
            rib, nullptr, nullptr, nullptr, nullptr, nullptr, nullptr, nullptr,
            x1d + 768 * 128, nullptr, nullptr, 768, 128);
    } else {
        const int r = b - 48;
        g64_flat(*(G64F*)raw, r % 6, r / 6, x1d, miw, mib, qkvd, 384);
    }
}

__global__ void __launch_bounds__(256, 1)
k_L5(const float* qkvd, float* fO, float* fM, float* fL,
     const float* x1d, const float* miw, const float* mib, float* qkvd_a)
{
    extern __shared__ char raw[];
    const int b = blockIdx.x;
    if (b < 144) {
        const int q = b / 48, rem = b % 48;
        flash_body(raw, q, rem / 12, (rem % 12) * 64, qkvd, fO, fM, fL);
    } else {
        const int r = b - 144;
        g64_flat(*(G64F*)raw, r % 6, r / 6,
                 x1d + 768 * 128, miw, mib, qkvd_a + 768 * QKVW, 384);
    }
}

__global__ void __launch_bounds__(256, 1)
k_L6(const float* qkvd, float* aod,
     const float* fO, const float* fM, const float* fL,
     const float* x1d, const float* mow, const float* mob, float* aopd)
{
    extern __shared__ char raw[];
    const int b = blockIdx.x;
    if (b < 60) {
        cls_body(raw, b % 15 + 1, b / 15, qkvd, aod);
    } else {
        const int r = b - 60;
        g32_flat<ACT_NONE, false, true, true, false>(
            *(G32F*)raw, r % 2, r / 2,
            nullptr, 128, mow, nullptr, 128,
            mob, nullptr, x1d, fO, fM, fL, nullptr, nullptr,
            aopd, nullptr, nullptr, 0, 128);
    }
}

__global__ void __launch_bounds__(256, 1)
k_L7(const float* aod, const float* x1d, const float* mow, const float* mob,
     float* aopd, const float* roww, const float* rob,
     const float* qw, float* qvp)
{
    extern __shared__ char raw[];
    const int b = blockIdx.x;
    if (b < 92) {
        g32_flat<ACT_NONE, false, true, false, false>(
            *(G32F*)raw, b % 2, b / 2,
            aod + 768 * 128, 128, mow, nullptr, 128,
            mob, nullptr, x1d, nullptr, nullptr, nullptr, nullptr, nullptr,
            aopd + 768 * 128, nullptr, nullptr, 768, 128);
    } else {
        const int r = b - 92;
        g32_flat<ACT_RELU, false, false, false, true>(
            *(G32F*)raw, r % 2, r / 2,
            aopd, 128, roww, nullptr, 128,
            rob, nullptr, nullptr, nullptr, nullptr, nullptr, qw, qvp,
            nullptr, nullptr, nullptr, 0, 128);
    }
}

__global__ void __launch_bounds__(256, 1)
k_L8(const float* aopd, const float* roww, const float* rob,
     const float* qw, float* qvp, const float* qb, float* out_q)
{
    extern __shared__ char raw[];
    g32_flat<ACT_RELU, false, false, false, true>(
        *(G32F*)raw, blockIdx.x % 2, blockIdx.x / 2,
        aopd + 768 * 128, 128, roww, nullptr, 128,
        rob, nullptr, nullptr, nullptr, nullptr, nullptr, qw, qvp,
        nullptr, nullptr, nullptr, 768, 128);

    __shared__ int is_last;
    __threadfence();
    __syncthreads();
    if (threadIdx.x == 0) is_last = (atomicAdd(&g_ctr, 1) == gridDim.x - 1);
    __syncthreads();
    if (is_last) {
        if (threadIdx.x == 0) g_ctr = 0;
        __threadfence();
        const float qb0 = qb[0];
        for (int l = threadIdx.x; l < 768; l += 256) {
            const int b = l >> 4, i = l & 15;
            float s = qvp[l] + qvp[MPOST + l] + qb0;
#pragma unroll
            for (int k = 1; k < 16; k++) {
                const int c = (i < k) ? 0 : 1;
                const int row = 768 + (k - 1) * 96 + b * 2 + c;
                s += qvp[row] + qvp[MPOST + row] + qb0;
            }
            out_q[l] = s;
        }
    }
}

extern "C" void kernel_launch(void* const* d_in, const int* in_sizes, int n_in,
                              void* d_out, int out_size)
{
    const float* obs = (const float*)d_in[0];
    const float* aw1 = (const float*)d_in[1];  const float* ab1 = (const float*)d_in[2];
    const float* aw2 = (const float*)d_in[3];  const float* ab2 = (const float*)d_in[4];
    const float* aw3 = (const float*)d_in[5];  const float* ab3 = (const float*)d_in[6];
    const float* eow = (const float*)d_in[7];  const float* eob = (const float*)d_in[8];
    const float* eaw = (const float*)d_in[9];  const float* eab = (const float*)d_in[10];
    const float* riw = (const float*)d_in[11]; const float* rib = (const float*)d_in[12];
    const float* roww = (const float*)d_in[13]; const float* rob = (const float*)d_in[14];
    const float* miw = (const float*)d_in[15]; const float* mib = (const float*)d_in[16];
    const float* mow = (const float*)d_in[17]; const float* mob = (const float*)d_in[18];
    const float* qw  = (const float*)d_in[19]; const float* qb  = (const float*)d_in[20];

    float* out = (float*)d_out;
    float* out_policy = out + OUT_POLICY;
    float* out_q      = out + OUT_Q;
    float* out_eo     = out + OUT_EO;

    float *H1, *H2p, *eaobs, *eoea, *x1d, *qkvd, *aod, *aopd, *qvp, *fO, *fM, *fL;
    cudaGetSymbolAddress((void**)&H1, g_H1);
    cudaGetSymbolAddress((void**)&H2p, g_H2p);
    cudaGetSymbolAddress((void**)&eaobs, g_eaobs);
    cudaGetSymbolAddress((void**)&eoea, g_eoea);
    cudaGetSymbolAddress((void**)&x1d, g_x1d);
    cudaGetSymbolAddress((void**)&qkvd, g_qkvd);
    cudaGetSymbolAddress((void**)&aod, g_aod);
    cudaGetSymbolAddress((void**)&aopd, g_aopd);
    cudaGetSymbolAddress((void**)&qvp, g_qvp);
    cudaGetSymbolAddress((void**)&fO, g_fO);
    cudaGetSymbolAddress((void**)&fM, g_fM);
    cudaGetSymbolAddress((void**)&fL, g_fL);

    const int sG32  = (int)sizeof(G32F);
    const int sL3   = (int)(sizeof(PoleaF) > sizeof(G32F) ? sizeof(PoleaF) : sizeof(G32F));
    const int sL45  = (int)(sizeof(G64F) > sizeof(FlashS) ? sizeof(G64F) : sizeof(FlashS));
    const int sL6   = (int)(sizeof(ClsS) > sizeof(G32F) ? sizeof(ClsS) : sizeof(G32F));

    cudaFuncSetAttribute(k_L1, cudaFuncAttributeMaxDynamicSharedMemorySize, sG32);
    cudaFuncSetAttribute(k_L2, cudaFuncAttributeMaxDynamicSharedMemorySize, sG32);
    cudaFuncSetAttribute(k_L3, cudaFuncAttributeMaxDynamicSharedMemorySize, sL3);
    cudaFuncSetAttribute(k_L4, cudaFuncAttributeMaxDynamicSharedMemorySize, sL45);
    cudaFuncSetAttribute(k_L5, cudaFuncAttributeMaxDynamicSharedMemorySize, sL45);
    cudaFuncSetAttribute(k_L6, cudaFuncAttributeMaxDynamicSharedMemorySize, sL6);
    cudaFuncSetAttribute(k_L7, cudaFuncAttributeMaxDynamicSharedMemorySize, sG32);
    cudaFuncSetAttribute(k_L8, cudaFuncAttributeMaxDynamicSharedMemorySize, sG32);

    dim3 blk(256);

    k_L1<<<144, blk, sG32>>>(obs, aw1, ab1, eow, eob, H1, out_eo, eoea);
    k_L2<<<144, blk, sG32>>>(H1, aw2, H2p, obs, eaw, eab, eaobs);
    k_L3<<<96,  blk, sL3 >>>(H2p, ab2, aw3, ab3, eaw, eaobs, out_policy, eoea,
                             riw, rib, x1d);
    k_L4<<<120, blk, sL45>>>(eoea, riw, rib, x1d, miw, mib, qkvd);
    k_L5<<<216, blk, sL45>>>(qkvd, fO, fM, fL, x1d, miw, mib, qkvd);
    k_L6<<<108, blk, sL6 >>>(qkvd, aod, fO, fM, fL, x1d, mow, mob, aopd);
    k_L7<<<140, blk, sG32>>>(aod, x1d, mow, mob, aopd, roww, rob, qw, qvp);
    k_L8<<<92,  blk, sG32>>>(aopd, roww, rob, qw, qvp, qb, out_q);

    (void)in_sizes; (void)n_in; (void)out_size;
}